// round 1
// baseline (speedup 1.0000x reference)
#include <cuda_runtime.h>
#include <math.h>

#define T_SEQ 4096
#define HID   2048
#define NH    16
#define NKV   2
#define HD    128
#define QKV_N ((NH + 2*NKV)*HD)   // 2560
#define GQA   (NH/NKV)            // 8

// Scratch (device globals: allocation-free per harness rules)
__device__ float g_qkv[4096 * 2560];     // 40 MB
__device__ float g_attn[4096 * 2048];    // 32 MB
__device__ float g_cos[4096 * 64];
__device__ float g_sin[4096 * 64];

// ---------------------------------------------------------------------------
// NT SGEMM: C[M,N] = A[M,K] @ B[N,K]^T (+ bias[n]).  M,N multiples of 64,
// K multiple of 16. 64x64 tile, BK=16, 256 threads, 4x4 per thread.
// ---------------------------------------------------------------------------
__global__ void __launch_bounds__(256)
gemm_nt(const float* __restrict__ A, const float* __restrict__ B,
        const float* __restrict__ bias, float* __restrict__ C,
        int M, int N, int K)
{
    __shared__ float As[16][64];
    __shared__ float Bs[16][64];

    const int tid = threadIdx.x;
    const int bm = blockIdx.y * 64;
    const int bn = blockIdx.x * 64;
    const int tx = tid & 15;
    const int ty = tid >> 4;
    const int lr = tid >> 2;          // 0..63 row within tile
    const int lc = (tid & 3) << 2;    // 0,4,8,12 k-offset

    float acc[4][4];
#pragma unroll
    for (int i = 0; i < 4; i++)
#pragma unroll
        for (int j = 0; j < 4; j++) acc[i][j] = 0.f;

    const float* Ap = A + (size_t)(bm + lr) * K + lc;
    const float* Bp = B + (size_t)(bn + lr) * K + lc;

    for (int k0 = 0; k0 < K; k0 += 16) {
        float4 a4 = *(const float4*)(Ap + k0);
        float4 b4 = *(const float4*)(Bp + k0);
        As[lc + 0][lr] = a4.x; As[lc + 1][lr] = a4.y;
        As[lc + 2][lr] = a4.z; As[lc + 3][lr] = a4.w;
        Bs[lc + 0][lr] = b4.x; Bs[lc + 1][lr] = b4.y;
        Bs[lc + 2][lr] = b4.z; Bs[lc + 3][lr] = b4.w;
        __syncthreads();
#pragma unroll
        for (int k = 0; k < 16; k++) {
            float4 av = *(const float4*)&As[k][ty * 4];
            float4 bv = *(const float4*)&Bs[k][tx * 4];
            acc[0][0] += av.x * bv.x; acc[0][1] += av.x * bv.y;
            acc[0][2] += av.x * bv.z; acc[0][3] += av.x * bv.w;
            acc[1][0] += av.y * bv.x; acc[1][1] += av.y * bv.y;
            acc[1][2] += av.y * bv.z; acc[1][3] += av.y * bv.w;
            acc[2][0] += av.z * bv.x; acc[2][1] += av.z * bv.y;
            acc[2][2] += av.z * bv.z; acc[2][3] += av.z * bv.w;
            acc[3][0] += av.w * bv.x; acc[3][1] += av.w * bv.y;
            acc[3][2] += av.w * bv.z; acc[3][3] += av.w * bv.w;
        }
        __syncthreads();
    }

    float b0 = 0.f, b1 = 0.f, b2 = 0.f, b3 = 0.f;
    if (bias) {
        b0 = bias[bn + tx * 4 + 0];
        b1 = bias[bn + tx * 4 + 1];
        b2 = bias[bn + tx * 4 + 2];
        b3 = bias[bn + tx * 4 + 3];
    }
#pragma unroll
    for (int i = 0; i < 4; i++) {
        float4 o;
        o.x = acc[i][0] + b0; o.y = acc[i][1] + b1;
        o.z = acc[i][2] + b2; o.w = acc[i][3] + b3;
        *(float4*)&C[(size_t)(bm + ty * 4 + i) * N + bn + tx * 4] = o;
    }
}

// ---------------------------------------------------------------------------
// RoPE cos/sin table (double precision so our angle is ~exact; the fp32
// reference rounding then bounds the mismatch well below 1e-3).
// ---------------------------------------------------------------------------
__global__ void rope_table_kernel(const int* __restrict__ pos,
                                  float* __restrict__ ct, float* __restrict__ st)
{
    int idx = blockIdx.x * blockDim.x + threadIdx.x;
    if (idx >= T_SEQ * (HD / 2)) return;
    int d = idx & 63;
    int t = idx >> 6;
    double inv = exp(-((double)(2 * d) / (double)HD) * 9.210340371976184); // ln(10000)
    double ang = (double)pos[t] * inv;
    ct[idx] = (float)cos(ang);
    st[idx] = (float)sin(ang);
}

// Apply rotate-half RoPE in-place to q (heads 0..15) and k (heads 16..17):
// both live at column h*HD in the qkv buffer since NH*HD == 2048.
__global__ void rope_apply_kernel(float* __restrict__ qkv,
                                  const float* __restrict__ ct,
                                  const float* __restrict__ st)
{
    int idx = blockIdx.x * blockDim.x + threadIdx.x;
    if (idx >= T_SEQ * (NH + NKV) * 64) return;
    int d = idx & 63;
    int h = (idx >> 6) % (NH + NKV);
    int t = idx / ((NH + NKV) * 64);
    float* base = qkv + (size_t)t * QKV_N + h * HD;
    float c = ct[t * 64 + d], s = st[t * 64 + d];
    float x1 = base[d], x2 = base[d + 64];
    base[d]      = x1 * c - x2 * s;
    base[d + 64] = x2 * c + x1 * s;
}

// ---------------------------------------------------------------------------
// Flash attention, fp32, causal, GQA 8:1.
// Block = (q-tile of 64 rows, head). 256 threads.
// smem: QT[128][64] (K-transposed, pre-scaled), KT[128][64], Vs[64][128],
//       Ss[64][68] (padded stride for conflict-free P reads).
// ---------------------------------------------------------------------------
#define BM 64
#define BN 64
#define SSTRIDE 68
#define ATTN_SMEM ((64*128*3 + 64*SSTRIDE) * 4)   // 115712 bytes

__global__ void __launch_bounds__(256)
attn_kernel(const float* __restrict__ qkv, float* __restrict__ out)
{
    extern __shared__ float smem[];
    float* QT = smem;             // [128][64]
    float* KT = smem + 8192;      // [128][64]
    float* Vs = smem + 16384;     // [64][128]
    float* Ss = smem + 24576;     // [64][68]

    const int h = blockIdx.y;
    const int qtile = (int)gridDim.x - 1 - (int)blockIdx.x; // heavy tiles first
    const int qbase = qtile * BM;
    const int g = h / GQA;
    const int qoff = h * HD;
    const int koff = NH * HD + g * HD;
    const int voff = (NH + NKV) * HD + g * HD;
    const int tid = threadIdx.x;
    const float scale = 0.08838834764831845f;  // 1/sqrt(128)

    // Load Q tile, transposed + pre-scaled.
#pragma unroll
    for (int u = 0; u < 8; u++) {
        int idx = tid + u * 256;        // float4 units
        int fr = idx >> 5;              // 0..63
        int fc = (idx & 31) << 2;       // 0..124 step 4
        float4 v = *(const float4*)&qkv[(size_t)(qbase + fr) * QKV_N + qoff + fc];
        QT[(fc + 0) * 64 + fr] = v.x * scale;
        QT[(fc + 1) * 64 + fr] = v.y * scale;
        QT[(fc + 2) * 64 + fr] = v.z * scale;
        QT[(fc + 3) * 64 + fr] = v.w * scale;
    }

    const int tx = tid & 15;
    const int ty = tid >> 4;
    const int r  = tid >> 2;   // output row 0..63
    const int q4 = tid & 3;    // quad lane

    float m = -INFINITY, l = 0.f;
    float acc[32];
#pragma unroll
    for (int i = 0; i < 32; i++) acc[i] = 0.f;

    for (int kt = 0; kt <= qtile; kt++) {
        const int kbase = kt * BN;
        __syncthreads();  // previous PV done before overwriting KT/Vs/Ss
        // Load K (transposed) and V tiles
#pragma unroll
        for (int u = 0; u < 8; u++) {
            int idx = tid + u * 256;
            int fr = idx >> 5;
            int fc = (idx & 31) << 2;
            const float* kp = &qkv[(size_t)(kbase + fr) * QKV_N];
            float4 kv = *(const float4*)(kp + koff + fc);
            KT[(fc + 0) * 64 + fr] = kv.x;
            KT[(fc + 1) * 64 + fr] = kv.y;
            KT[(fc + 2) * 64 + fr] = kv.z;
            KT[(fc + 3) * 64 + fr] = kv.w;
            float4 vv = *(const float4*)(kp + voff + fc);
            *(float4*)&Vs[fr * HD + fc] = vv;
        }
        __syncthreads();

        // S = (Q*scale) @ K^T   (4x4 per thread)
        float s[4][4];
#pragma unroll
        for (int i = 0; i < 4; i++)
#pragma unroll
            for (int j = 0; j < 4; j++) s[i][j] = 0.f;
#pragma unroll 8
        for (int k = 0; k < HD; k++) {
            float4 a = *(const float4*)&QT[k * 64 + ty * 4];
            float4 b = *(const float4*)&KT[k * 64 + tx * 4];
            s[0][0] += a.x * b.x; s[0][1] += a.x * b.y;
            s[0][2] += a.x * b.z; s[0][3] += a.x * b.w;
            s[1][0] += a.y * b.x; s[1][1] += a.y * b.y;
            s[1][2] += a.y * b.z; s[1][3] += a.y * b.w;
            s[2][0] += a.z * b.x; s[2][1] += a.z * b.y;
            s[2][2] += a.z * b.z; s[2][3] += a.z * b.w;
            s[3][0] += a.w * b.x; s[3][1] += a.w * b.y;
            s[3][2] += a.w * b.z; s[3][3] += a.w * b.w;
        }
        // causal mask (only the diagonal tile needs it) + store to Ss
        const bool diag = (kt == qtile);
#pragma unroll
        for (int i = 0; i < 4; i++) {
            int rg = qbase + ty * 4 + i;
#pragma unroll
            for (int j = 0; j < 4; j++) {
                int cg = kbase + tx * 4 + j;
                float val = (diag && cg > rg) ? -1e30f : s[i][j];
                Ss[(ty * 4 + i) * SSTRIDE + tx * 4 + j] = val;
            }
        }
        __syncthreads();

        // Online softmax: row r handled by its 4-lane quad (16 cols each)
        float* prow = &Ss[r * SSTRIDE + q4 * 16];
        float tmax = -INFINITY;
#pragma unroll
        for (int c = 0; c < 16; c++) tmax = fmaxf(tmax, prow[c]);
        tmax = fmaxf(tmax, __shfl_xor_sync(0xffffffffu, tmax, 1));
        tmax = fmaxf(tmax, __shfl_xor_sync(0xffffffffu, tmax, 2));
        float mnew = fmaxf(m, tmax);
        float corr = __expf(m - mnew);
        float rsum = 0.f;
#pragma unroll
        for (int c = 0; c < 16; c++) {
            float p = __expf(prow[c] - mnew);
            prow[c] = p;
            rsum += p;
        }
        rsum += __shfl_xor_sync(0xffffffffu, rsum, 1);
        rsum += __shfl_xor_sync(0xffffffffu, rsum, 2);
#pragma unroll
        for (int i = 0; i < 32; i++) acc[i] *= corr;
        l = l * corr + rsum;
        m = mnew;
        __syncwarp();  // P row written by this quad only -> warp-scope is enough

        // O += P @ V ; thread owns cols {cc*16 + q4*4 + e}
#pragma unroll 2
        for (int j = 0; j < BN; j++) {
            float p = Ss[r * SSTRIDE + j];
#pragma unroll
            for (int cc = 0; cc < 8; cc++) {
                float4 v = *(const float4*)&Vs[j * HD + cc * 16 + q4 * 4];
                acc[cc * 4 + 0] += p * v.x;
                acc[cc * 4 + 1] += p * v.y;
                acc[cc * 4 + 2] += p * v.z;
                acc[cc * 4 + 3] += p * v.w;
            }
        }
    }

    // Epilogue: O /= l
    float invl = 1.f / l;
    float* op = out + (size_t)(qbase + r) * HID + h * HD;
#pragma unroll
    for (int cc = 0; cc < 8; cc++) {
        float4 o;
        o.x = acc[cc * 4 + 0] * invl;
        o.y = acc[cc * 4 + 1] * invl;
        o.z = acc[cc * 4 + 2] * invl;
        o.w = acc[cc * 4 + 3] * invl;
        *(float4*)&op[cc * 16 + q4 * 4] = o;
    }
}

// ---------------------------------------------------------------------------
extern "C" void kernel_launch(void* const* d_in, const int* in_sizes, int n_in,
                              void* d_out, int out_size)
{
    const int*   positions = (const int*)d_in[0];
    const float* hidden    = (const float*)d_in[1];
    const float* w_qkv     = (const float*)d_in[2];
    const float* b_qkv     = (const float*)d_in[3];
    const float* w_o       = (const float*)d_in[4];
    float* out = (float*)d_out;

    float *qkv, *attn, *ct, *st;
    cudaGetSymbolAddress((void**)&qkv,  g_qkv);
    cudaGetSymbolAddress((void**)&attn, g_attn);
    cudaGetSymbolAddress((void**)&ct,   g_cos);
    cudaGetSymbolAddress((void**)&st,   g_sin);

    // 1) qkv = hidden @ w_qkv^T + b_qkv
    dim3 g1(QKV_N / 64, T_SEQ / 64);
    gemm_nt<<<g1, 256>>>(hidden, w_qkv, b_qkv, qkv, T_SEQ, QKV_N, HID);

    // 2) RoPE table + apply
    int nt = T_SEQ * (HD / 2);
    rope_table_kernel<<<(nt + 255) / 256, 256>>>(positions, ct, st);
    int na = T_SEQ * (NH + NKV) * 64;
    rope_apply_kernel<<<(na + 255) / 256, 256>>>(qkv, ct, st);

    // 3) causal flash attention
    cudaFuncSetAttribute(attn_kernel,
                         cudaFuncAttributeMaxDynamicSharedMemorySize, ATTN_SMEM);
    attn_kernel<<<dim3(T_SEQ / 64, NH), 256, ATTN_SMEM>>>(qkv, attn);

    // 4) out = attn @ w_o^T
    dim3 g2(HID / 64, T_SEQ / 64);
    gemm_nt<<<g2, 256>>>(attn, w_o, nullptr, out, T_SEQ, HID, HID);
}

// round 3
// speedup vs baseline: 1.2517x; 1.2517x over previous
#include <cuda_runtime.h>
#include <cuda_bf16.h>
#include <math.h>
#include <stdint.h>

#define T_SEQ 4096
#define HID   2048
#define NH    16
#define NKV   2
#define HD    128
#define QKV_N ((NH + 2*NKV)*HD)   // 2560
#define GQA   (NH/NKV)            // 8

// Scratch (device globals: allocation-free per harness rules)
__device__ float g_qkv[4096 * 2560];     // 40 MB
__device__ float g_attn[4096 * 2048];    // 32 MB
__device__ float g_cos[4096 * 64];
__device__ float g_sin[4096 * 64];

// ===========================================================================
// HMMA helpers (sm_80-class ISA: assemblable at plain sm_103 target)
// ===========================================================================
__device__ __forceinline__ uint32_t su32(const void* p) {
    uint32_t a;
    asm("{ .reg .u64 t; cvta.to.shared.u64 t, %1; cvt.u32.u64 %0, t; }"
        : "=r"(a) : "l"(p));
    return a;
}

__device__ __forceinline__ void ldsm4(uint32_t* r, uint32_t addr) {
    asm volatile("ldmatrix.sync.aligned.m8n8.x4.shared.b16 {%0,%1,%2,%3}, [%4];"
                 : "=r"(r[0]), "=r"(r[1]), "=r"(r[2]), "=r"(r[3]) : "r"(addr));
}

__device__ __forceinline__ void mma16816(float* c, const uint32_t* a,
                                         uint32_t b0, uint32_t b1) {
    asm volatile(
        "mma.sync.aligned.m16n8k16.row.col.f32.bf16.bf16.f32 "
        "{%0,%1,%2,%3}, {%4,%5,%6,%7}, {%8,%9}, {%0,%1,%2,%3};"
        : "+f"(c[0]), "+f"(c[1]), "+f"(c[2]), "+f"(c[3])
        : "r"(a[0]), "r"(a[1]), "r"(a[2]), "r"(a[3]), "r"(b0), "r"(b1));
}

// ===========================================================================
// HMMA NT GEMM: C[M,N] = A[M,K] @ B[N,K]^T (+bias). bf16 hi/lo split, 3 terms
// (AhBh + AhBl + AlBh) -> ~1e-5 rel err with fp32 accumulate.
// Tile 128x128, BK=32, 8 warps (warp tile 32x64). Smem stride 40 bf16 kills
// ldmatrix bank conflicts (rows 20 banks apart -> all distinct mod 32).
// ===========================================================================
#define GS 40

__global__ void __launch_bounds__(256)
gemm_mma(const float* __restrict__ A, const float* __restrict__ B,
         const float* __restrict__ bias, float* __restrict__ C,
         int M, int N, int K)
{
    __shared__ __nv_bfloat16 Ah[128 * GS], Al[128 * GS];
    __shared__ __nv_bfloat16 Bh[128 * GS], Bl[128 * GS];

    const int tid  = threadIdx.x;
    const int wid  = tid >> 5;
    const int lane = tid & 31;
    const int bm = blockIdx.y * 128;
    const int bn = blockIdx.x * 128;
    const int wm = (wid & 3) * 32;    // warp m offset
    const int wn = (wid >> 2) * 64;   // warp n offset

    float acc[2][8][4];
#pragma unroll
    for (int i = 0; i < 2; i++)
#pragma unroll
        for (int n = 0; n < 8; n++)
#pragma unroll
            for (int e = 0; e < 4; e++) acc[i][n][e] = 0.f;

    const int lrow = tid >> 1;        // 0..127
    const int lcol = (tid & 1) * 16;  // 0 or 16

    // ldmatrix base addresses (lane-dependent parts precomputed)
    const int a_r = lane & 15;        // A: rows 0..15, k half by lane>>4
    const int a_k = (lane >> 4) * 8;
    const int b_n = ((lane >> 3) & 1) * 8 + (lane & 7);  // B: n row within n16
    const int b_k = (lane >> 4) * 8;

    for (int s = 0; s < K; s += 32) {
        __syncthreads();
        const float* ap = A + (size_t)(bm + lrow) * K + s + lcol;
        const float* bp = B + (size_t)(bn + lrow) * K + s + lcol;
#pragma unroll
        for (int j = 0; j < 4; j++) {
            float4 a4 = *(const float4*)(ap + j * 4);
            float4 b4 = *(const float4*)(bp + j * 4);
            __nv_bfloat16 h0 = __float2bfloat16_rn(a4.x);
            __nv_bfloat16 h1 = __float2bfloat16_rn(a4.y);
            __nv_bfloat16 h2 = __float2bfloat16_rn(a4.z);
            __nv_bfloat16 h3 = __float2bfloat16_rn(a4.w);
            uint64_t wh = (uint64_t)__bfloat16_as_ushort(h0)
                        | ((uint64_t)__bfloat16_as_ushort(h1) << 16)
                        | ((uint64_t)__bfloat16_as_ushort(h2) << 32)
                        | ((uint64_t)__bfloat16_as_ushort(h3) << 48);
            __nv_bfloat16 l0 = __float2bfloat16_rn(a4.x - __bfloat162float(h0));
            __nv_bfloat16 l1 = __float2bfloat16_rn(a4.y - __bfloat162float(h1));
            __nv_bfloat16 l2 = __float2bfloat16_rn(a4.z - __bfloat162float(h2));
            __nv_bfloat16 l3 = __float2bfloat16_rn(a4.w - __bfloat162float(h3));
            uint64_t wl = (uint64_t)__bfloat16_as_ushort(l0)
                        | ((uint64_t)__bfloat16_as_ushort(l1) << 16)
                        | ((uint64_t)__bfloat16_as_ushort(l2) << 32)
                        | ((uint64_t)__bfloat16_as_ushort(l3) << 48);
            int off = lrow * GS + lcol + j * 4;
            *(uint64_t*)&Ah[off] = wh;
            *(uint64_t*)&Al[off] = wl;

            __nv_bfloat16 g0 = __float2bfloat16_rn(b4.x);
            __nv_bfloat16 g1 = __float2bfloat16_rn(b4.y);
            __nv_bfloat16 g2 = __float2bfloat16_rn(b4.z);
            __nv_bfloat16 g3 = __float2bfloat16_rn(b4.w);
            uint64_t vh = (uint64_t)__bfloat16_as_ushort(g0)
                        | ((uint64_t)__bfloat16_as_ushort(g1) << 16)
                        | ((uint64_t)__bfloat16_as_ushort(g2) << 32)
                        | ((uint64_t)__bfloat16_as_ushort(g3) << 48);
            __nv_bfloat16 m0 = __float2bfloat16_rn(b4.x - __bfloat162float(g0));
            __nv_bfloat16 m1 = __float2bfloat16_rn(b4.y - __bfloat162float(g1));
            __nv_bfloat16 m2 = __float2bfloat16_rn(b4.z - __bfloat162float(g2));
            __nv_bfloat16 m3 = __float2bfloat16_rn(b4.w - __bfloat162float(g3));
            uint64_t vl = (uint64_t)__bfloat16_as_ushort(m0)
                        | ((uint64_t)__bfloat16_as_ushort(m1) << 16)
                        | ((uint64_t)__bfloat16_as_ushort(m2) << 32)
                        | ((uint64_t)__bfloat16_as_ushort(m3) << 48);
            *(uint64_t*)&Bh[off] = vh;
            *(uint64_t*)&Bl[off] = vl;
        }
        __syncthreads();

#pragma unroll
        for (int kk = 0; kk < 32; kk += 16) {
            uint32_t ah[2][4], al[2][4];
#pragma unroll
            for (int i = 0; i < 2; i++) {
                int arow = wm + i * 16 + a_r;
                ldsm4(ah[i], su32(&Ah[arow * GS + kk + a_k]));
                ldsm4(al[i], su32(&Al[arow * GS + kk + a_k]));
            }
#pragma unroll
            for (int np = 0; np < 4; np++) {
                int brow = wn + np * 16 + b_n;
                uint32_t bh[4], bl[4];
                ldsm4(bh, su32(&Bh[brow * GS + kk + b_k]));
                ldsm4(bl, su32(&Bl[brow * GS + kk + b_k]));
#pragma unroll
                for (int i = 0; i < 2; i++) {
                    mma16816(acc[i][np * 2],     ah[i], bh[0], bh[2]);
                    mma16816(acc[i][np * 2 + 1], ah[i], bh[1], bh[3]);
                    mma16816(acc[i][np * 2],     ah[i], bl[0], bl[2]);
                    mma16816(acc[i][np * 2 + 1], ah[i], bl[1], bl[3]);
                    mma16816(acc[i][np * 2],     al[i], bh[0], bh[2]);
                    mma16816(acc[i][np * 2 + 1], al[i], bh[1], bh[3]);
                }
            }
        }
    }

    // Epilogue: c frag thread mapping: rows lane/4 (+8), cols (lane%4)*2 (+1)
    const int tr = lane >> 2;
    const int tc = (lane & 3) * 2;
#pragma unroll
    for (int i = 0; i < 2; i++) {
#pragma unroll
        for (int n = 0; n < 8; n++) {
            int col = bn + wn + n * 8 + tc;
            float bb0 = bias ? bias[col]     : 0.f;
            float bb1 = bias ? bias[col + 1] : 0.f;
            int row0 = bm + wm + i * 16 + tr;
            float2 v0 = make_float2(acc[i][n][0] + bb0, acc[i][n][1] + bb1);
            float2 v1 = make_float2(acc[i][n][2] + bb0, acc[i][n][3] + bb1);
            *(float2*)&C[(size_t)row0 * N + col]       = v0;
            *(float2*)&C[(size_t)(row0 + 8) * N + col] = v1;
        }
    }
}

// ---------------------------------------------------------------------------
// RoPE cos/sin table (double precision angles)
// ---------------------------------------------------------------------------
__global__ void rope_table_kernel(const int* __restrict__ pos,
                                  float* __restrict__ ct, float* __restrict__ st)
{
    int idx = blockIdx.x * blockDim.x + threadIdx.x;
    if (idx >= T_SEQ * (HD / 2)) return;
    int d = idx & 63;
    int t = idx >> 6;
    double inv = exp(-((double)(2 * d) / (double)HD) * 9.210340371976184); // ln(10000)
    double ang = (double)pos[t] * inv;
    ct[idx] = (float)cos(ang);
    st[idx] = (float)sin(ang);
}

__global__ void rope_apply_kernel(float* __restrict__ qkv,
                                  const float* __restrict__ ct,
                                  const float* __restrict__ st)
{
    int idx = blockIdx.x * blockDim.x + threadIdx.x;
    if (idx >= T_SEQ * (NH + NKV) * 64) return;
    int d = idx & 63;
    int h = (idx >> 6) % (NH + NKV);
    int t = idx / ((NH + NKV) * 64);
    float* base = qkv + (size_t)t * QKV_N + h * HD;
    float c = ct[t * 64 + d], s = st[t * 64 + d];
    float x1 = base[d], x2 = base[d + 64];
    base[d]      = x1 * c - x2 * s;
    base[d + 64] = x2 * c + x1 * s;
}

// ---------------------------------------------------------------------------
// Flash attention, fp32, causal, GQA 8:1 (R1 version, known good)
// ---------------------------------------------------------------------------
#define BM 64
#define BN 64
#define SSTRIDE 68
#define ATTN_SMEM ((64*128*3 + 64*SSTRIDE) * 4)   // 115712 bytes

__global__ void __launch_bounds__(256)
attn_kernel(const float* __restrict__ qkv, float* __restrict__ out)
{
    extern __shared__ float smem[];
    float* QT = smem;             // [128][64]
    float* KT = smem + 8192;      // [128][64]
    float* Vs = smem + 16384;     // [64][128]
    float* Ss = smem + 24576;     // [64][68]

    const int h = blockIdx.y;
    const int qtile = (int)gridDim.x - 1 - (int)blockIdx.x; // heavy tiles first
    const int qbase = qtile * BM;
    const int g = h / GQA;
    const int qoff = h * HD;
    const int koff = NH * HD + g * HD;
    const int voff = (NH + NKV) * HD + g * HD;
    const int tid = threadIdx.x;
    const float scale = 0.08838834764831845f;  // 1/sqrt(128)

#pragma unroll
    for (int u = 0; u < 8; u++) {
        int idx = tid + u * 256;
        int fr = idx >> 5;
        int fc = (idx & 31) << 2;
        float4 v = *(const float4*)&qkv[(size_t)(qbase + fr) * QKV_N + qoff + fc];
        QT[(fc + 0) * 64 + fr] = v.x * scale;
        QT[(fc + 1) * 64 + fr] = v.y * scale;
        QT[(fc + 2) * 64 + fr] = v.z * scale;
        QT[(fc + 3) * 64 + fr] = v.w * scale;
    }

    const int tx = tid & 15;
    const int ty = tid >> 4;
    const int r  = tid >> 2;
    const int q4 = tid & 3;

    float m = -INFINITY, l = 0.f;
    float acc[32];
#pragma unroll
    for (int i = 0; i < 32; i++) acc[i] = 0.f;

    for (int kt = 0; kt <= qtile; kt++) {
        const int kbase = kt * BN;
        __syncthreads();
#pragma unroll
        for (int u = 0; u < 8; u++) {
            int idx = tid + u * 256;
            int fr = idx >> 5;
            int fc = (idx & 31) << 2;
            const float* kp = &qkv[(size_t)(kbase + fr) * QKV_N];
            float4 kv = *(const float4*)(kp + koff + fc);
            KT[(fc + 0) * 64 + fr] = kv.x;
            KT[(fc + 1) * 64 + fr] = kv.y;
            KT[(fc + 2) * 64 + fr] = kv.z;
            KT[(fc + 3) * 64 + fr] = kv.w;
            float4 vv = *(const float4*)(kp + voff + fc);
            *(float4*)&Vs[fr * HD + fc] = vv;
        }
        __syncthreads();

        float s[4][4];
#pragma unroll
        for (int i = 0; i < 4; i++)
#pragma unroll
            for (int j = 0; j < 4; j++) s[i][j] = 0.f;
#pragma unroll 8
        for (int k = 0; k < HD; k++) {
            float4 a = *(const float4*)&QT[k * 64 + ty * 4];
            float4 b = *(const float4*)&KT[k * 64 + tx * 4];
            s[0][0] += a.x * b.x; s[0][1] += a.x * b.y;
            s[0][2] += a.x * b.z; s[0][3] += a.x * b.w;
            s[1][0] += a.y * b.x; s[1][1] += a.y * b.y;
            s[1][2] += a.y * b.z; s[1][3] += a.y * b.w;
            s[2][0] += a.z * b.x; s[2][1] += a.z * b.y;
            s[2][2] += a.z * b.z; s[2][3] += a.z * b.w;
            s[3][0] += a.w * b.x; s[3][1] += a.w * b.y;
            s[3][2] += a.w * b.z; s[3][3] += a.w * b.w;
        }
        const bool diag = (kt == qtile);
#pragma unroll
        for (int i = 0; i < 4; i++) {
            int rg = qbase + ty * 4 + i;
#pragma unroll
            for (int j = 0; j < 4; j++) {
                int cg = kbase + tx * 4 + j;
                float val = (diag && cg > rg) ? -1e30f : s[i][j];
                Ss[(ty * 4 + i) * SSTRIDE + tx * 4 + j] = val;
            }
        }
        __syncthreads();

        float* prow = &Ss[r * SSTRIDE + q4 * 16];
        float tmax = -INFINITY;
#pragma unroll
        for (int c = 0; c < 16; c++) tmax = fmaxf(tmax, prow[c]);
        tmax = fmaxf(tmax, __shfl_xor_sync(0xffffffffu, tmax, 1));
        tmax = fmaxf(tmax, __shfl_xor_sync(0xffffffffu, tmax, 2));
        float mnew = fmaxf(m, tmax);
        float corr = __expf(m - mnew);
        float rsum = 0.f;
#pragma unroll
        for (int c = 0; c < 16; c++) {
            float p = __expf(prow[c] - mnew);
            prow[c] = p;
            rsum += p;
        }
        rsum += __shfl_xor_sync(0xffffffffu, rsum, 1);
        rsum += __shfl_xor_sync(0xffffffffu, rsum, 2);
#pragma unroll
        for (int i = 0; i < 32; i++) acc[i] *= corr;
        l = l * corr + rsum;
        m = mnew;
        __syncwarp();

#pragma unroll 2
        for (int j = 0; j < BN; j++) {
            float p = Ss[r * SSTRIDE + j];
#pragma unroll
            for (int cc = 0; cc < 8; cc++) {
                float4 v = *(const float4*)&Vs[j * HD + cc * 16 + q4 * 4];
                acc[cc * 4 + 0] += p * v.x;
                acc[cc * 4 + 1] += p * v.y;
                acc[cc * 4 + 2] += p * v.z;
                acc[cc * 4 + 3] += p * v.w;
            }
        }
    }

    float invl = 1.f / l;
    float* op = out + (size_t)(qbase + r) * HID + h * HD;
#pragma unroll
    for (int cc = 0; cc < 8; cc++) {
        float4 o;
        o.x = acc[cc * 4 + 0] * invl;
        o.y = acc[cc * 4 + 1] * invl;
        o.z = acc[cc * 4 + 2] * invl;
        o.w = acc[cc * 4 + 3] * invl;
        *(float4*)&op[cc * 16 + q4 * 4] = o;
    }
}

// ---------------------------------------------------------------------------
extern "C" void kernel_launch(void* const* d_in, const int* in_sizes, int n_in,
                              void* d_out, int out_size)
{
    const int*   positions = (const int*)d_in[0];
    const float* hidden    = (const float*)d_in[1];
    const float* w_qkv     = (const float*)d_in[2];
    const float* b_qkv     = (const float*)d_in[3];
    const float* w_o       = (const float*)d_in[4];
    float* out = (float*)d_out;

    float *qkv, *attn, *ct, *st;
    cudaGetSymbolAddress((void**)&qkv,  g_qkv);
    cudaGetSymbolAddress((void**)&attn, g_attn);
    cudaGetSymbolAddress((void**)&ct,   g_cos);
    cudaGetSymbolAddress((void**)&st,   g_sin);

    // 1) qkv = hidden @ w_qkv^T + b_qkv   (HMMA bf16-split x3)
    dim3 g1(QKV_N / 128, T_SEQ / 128);
    gemm_mma<<<g1, 256>>>(hidden, w_qkv, b_qkv, qkv, T_SEQ, QKV_N, HID);

    // 2) RoPE table + apply
    int nt = T_SEQ * (HD / 2);
    rope_table_kernel<<<(nt + 255) / 256, 256>>>(positions, ct, st);
    int na = T_SEQ * (NH + NKV) * 64;
    rope_apply_kernel<<<(na + 255) / 256, 256>>>(qkv, ct, st);

    // 3) causal flash attention (fp32, unchanged)
    cudaFuncSetAttribute(attn_kernel,
                         cudaFuncAttributeMaxDynamicSharedMemorySize, ATTN_SMEM);
    attn_kernel<<<dim3(T_SEQ / 64, NH), 256, ATTN_SMEM>>>(qkv, attn);

    // 4) out = attn @ w_o^T   (HMMA)
    dim3 g2(HID / 128, T_SEQ / 128);
    gemm_mma<<<g2, 256>>>(attn, w_o, nullptr, out, T_SEQ, HID, HID);
}

// round 4
// speedup vs baseline: 4.3767x; 3.4968x over previous
#include <cuda_runtime.h>
#include <cuda_bf16.h>
#include <math.h>
#include <stdint.h>

#define T_SEQ 4096
#define HID   2048
#define NH    16
#define NKV   2
#define HD    128
#define QKV_N ((NH + 2*NKV)*HD)   // 2560
#define GQA   (NH/NKV)            // 8

// ---------------------------------------------------------------------------
// Device-global scratch (allocation-free rules)
// ---------------------------------------------------------------------------
__device__ float g_qkv[4096 * 2560];                 // fp32 qkv (for RoPE)
__device__ __nv_bfloat16 g_hidh[4096 * 2048], g_hidl[4096 * 2048];
__device__ __nv_bfloat16 g_wqh[2560 * 2048],  g_wql[2560 * 2048];
__device__ __nv_bfloat16 g_woh[2048 * 2048],  g_wol[2048 * 2048];
__device__ __nv_bfloat16 g_qkvh[4096 * 2560], g_qkvl[4096 * 2560];
__device__ __nv_bfloat16 g_attnh[4096 * 2048], g_attnl[4096 * 2048];
__device__ float g_cos[4096 * 64];
__device__ float g_sin[4096 * 64];

// ---------------------------------------------------------------------------
// Helpers
// ---------------------------------------------------------------------------
__device__ __forceinline__ uint32_t su32(const void* p) {
    uint32_t a;
    asm("{ .reg .u64 t; cvta.to.shared.u64 t, %1; cvt.u32.u64 %0, t; }"
        : "=r"(a) : "l"(p));
    return a;
}
__device__ __forceinline__ void ldsm4(uint32_t* r, uint32_t addr) {
    asm volatile("ldmatrix.sync.aligned.m8n8.x4.shared.b16 {%0,%1,%2,%3}, [%4];"
                 : "=r"(r[0]), "=r"(r[1]), "=r"(r[2]), "=r"(r[3]) : "r"(addr));
}
__device__ __forceinline__ void ldsm4t(uint32_t* r, uint32_t addr) {
    asm volatile("ldmatrix.sync.aligned.m8n8.x4.trans.shared.b16 {%0,%1,%2,%3}, [%4];"
                 : "=r"(r[0]), "=r"(r[1]), "=r"(r[2]), "=r"(r[3]) : "r"(addr));
}
__device__ __forceinline__ void mma16816(float* c, const uint32_t* a,
                                         uint32_t b0, uint32_t b1) {
    asm volatile(
        "mma.sync.aligned.m16n8k16.row.col.f32.bf16.bf16.f32 "
        "{%0,%1,%2,%3}, {%4,%5,%6,%7}, {%8,%9}, {%0,%1,%2,%3};"
        : "+f"(c[0]), "+f"(c[1]), "+f"(c[2]), "+f"(c[3])
        : "r"(a[0]), "r"(a[1]), "r"(a[2]), "r"(a[3]), "r"(b0), "r"(b1));
}
__device__ __forceinline__ void cp_async8(uint32_t smem, const void* g) {
    asm volatile("cp.async.ca.shared.global [%0], [%1], 8;" :: "r"(smem), "l"(g));
}
__device__ __forceinline__ void cp_async16(uint32_t smem, const void* g) {
    asm volatile("cp.async.cg.shared.global [%0], [%1], 16;" :: "r"(smem), "l"(g));
}
#define CP_COMMIT() asm volatile("cp.async.commit_group;" ::: "memory")
#define CP_WAIT0()  asm volatile("cp.async.wait_group 0;" ::: "memory")
#define CP_WAIT1()  asm volatile("cp.async.wait_group 1;" ::: "memory")

__device__ __forceinline__ float ex2f(float x) {
    float y;
    asm("ex2.approx.ftz.f32 %0, %1;" : "=f"(y) : "f"(x));
    return y;
}
__device__ __forceinline__ uint32_t packbf(float x, float y) {
    __nv_bfloat162 t = __floats2bfloat162_rn(x, y);
    return *(uint32_t*)&t;
}

// ---------------------------------------------------------------------------
// fp32 -> bf16 hi/lo split kernels
// ---------------------------------------------------------------------------
__device__ __forceinline__ void split4(float4 v, __nv_bfloat16* hi, __nv_bfloat16* lo) {
    __nv_bfloat16 h0 = __float2bfloat16_rn(v.x), h1 = __float2bfloat16_rn(v.y);
    __nv_bfloat16 h2 = __float2bfloat16_rn(v.z), h3 = __float2bfloat16_rn(v.w);
    uint64_t wh = (uint64_t)__bfloat16_as_ushort(h0)
                | ((uint64_t)__bfloat16_as_ushort(h1) << 16)
                | ((uint64_t)__bfloat16_as_ushort(h2) << 32)
                | ((uint64_t)__bfloat16_as_ushort(h3) << 48);
    __nv_bfloat16 l0 = __float2bfloat16_rn(v.x - __bfloat162float(h0));
    __nv_bfloat16 l1 = __float2bfloat16_rn(v.y - __bfloat162float(h1));
    __nv_bfloat16 l2 = __float2bfloat16_rn(v.z - __bfloat162float(h2));
    __nv_bfloat16 l3 = __float2bfloat16_rn(v.w - __bfloat162float(h3));
    uint64_t wl = (uint64_t)__bfloat16_as_ushort(l0)
                | ((uint64_t)__bfloat16_as_ushort(l1) << 16)
                | ((uint64_t)__bfloat16_as_ushort(l2) << 32)
                | ((uint64_t)__bfloat16_as_ushort(l3) << 48);
    *(uint64_t*)hi = wh;
    *(uint64_t*)lo = wl;
}

__global__ void split_plain(const float* __restrict__ in,
                            __nv_bfloat16* __restrict__ hi,
                            __nv_bfloat16* __restrict__ lo, int n)
{
    int i = (blockIdx.x * blockDim.x + threadIdx.x) * 4;
    if (i >= n) return;
    split4(*(const float4*)(in + i), hi + i, lo + i);
}

// qkv split: fold attention scale * log2(e) into q columns (<2048)
#define QSC (0.08838834764831845f * 1.4426950408889634f)
__global__ void split_qkv_kernel(const float* __restrict__ in,
                                 __nv_bfloat16* __restrict__ hi,
                                 __nv_bfloat16* __restrict__ lo)
{
    int i = (blockIdx.x * blockDim.x + threadIdx.x) * 4;
    if (i >= T_SEQ * QKV_N) return;
    float4 v = *(const float4*)(in + i);
    int col = i % QKV_N;
    if (col < 2048) { v.x *= QSC; v.y *= QSC; v.z *= QSC; v.w *= QSC; }
    split4(v, hi + i, lo + i);
}

// ===========================================================================
// bf16 hi/lo GEMM (3-term): C[M,N] = (Ah+Al)[M,K] @ (Bh+Bl)[N,K]^T (+bias)
// Tile 128x128, BK=32, 8 warps, cp.async double-buffered, stride 40 (pad)
// ===========================================================================
#define GS 40
#define GB_STAGE (4 * 128 * GS)            // bf16 units per stage
#define GB_SMEM  (2 * GB_STAGE * 2)        // bytes = 81920

__global__ void __launch_bounds__(256)
gemm_bf(const __nv_bfloat16* __restrict__ Ah_g, const __nv_bfloat16* __restrict__ Al_g,
        const __nv_bfloat16* __restrict__ Bh_g, const __nv_bfloat16* __restrict__ Bl_g,
        const float* __restrict__ bias, float* __restrict__ C,
        int M, int N, int K)
{
    extern __shared__ __nv_bfloat16 smg[];
    const int tid = threadIdx.x, wid = tid >> 5, lane = tid & 31;
    const int bm = blockIdx.y * 128, bn = blockIdx.x * 128;
    const int wm = (wid & 3) * 32, wn = (wid >> 2) * 64;

    float acc[2][8][4];
#pragma unroll
    for (int i = 0; i < 2; i++)
#pragma unroll
        for (int n = 0; n < 8; n++)
#pragma unroll
            for (int e = 0; e < 4; e++) acc[i][n][e] = 0.f;

    const int S = K / 32;

    auto issue = [&](int buf, int s) {
        __nv_bfloat16* base = smg + buf * GB_STAGE;
        const int k0 = s * 32;
#pragma unroll
        for (int i = 0; i < 16; i++) {
            int c = tid + i * 256;
            int mat = c >> 10;          // 0 Ah, 1 Al, 2 Bh, 3 Bl
            int w = c & 1023;
            int row = w >> 3, cc = w & 7;
            const __nv_bfloat16* src =
                (mat == 0) ? Ah_g + (size_t)(bm + row) * K + k0 + cc * 4 :
                (mat == 1) ? Al_g + (size_t)(bm + row) * K + k0 + cc * 4 :
                (mat == 2) ? Bh_g + (size_t)(bn + row) * K + k0 + cc * 4 :
                             Bl_g + (size_t)(bn + row) * K + k0 + cc * 4;
            cp_async8(su32(base + mat * (128 * GS) + row * GS + cc * 4), src);
        }
    };

    issue(0, 0); CP_COMMIT();

    const int a_r = lane & 15, a_k = (lane >> 4) * 8;
    const int b_n = ((lane >> 3) & 1) * 8 + (lane & 7), b_k = (lane >> 4) * 8;

    for (int s = 0; s < S; s++) {
        if (s + 1 < S) { issue((s + 1) & 1, s + 1); CP_COMMIT(); CP_WAIT1(); }
        else CP_WAIT0();
        __syncthreads();

        __nv_bfloat16* Ah = smg + (s & 1) * GB_STAGE;
        __nv_bfloat16* Al = Ah + 128 * GS;
        __nv_bfloat16* Bh = Al + 128 * GS;
        __nv_bfloat16* Bl = Bh + 128 * GS;

#pragma unroll
        for (int kk = 0; kk < 32; kk += 16) {
            uint32_t ah[2][4], al[2][4];
#pragma unroll
            for (int i = 0; i < 2; i++) {
                int ar = wm + i * 16 + a_r;
                ldsm4(ah[i], su32(&Ah[ar * GS + kk + a_k]));
                ldsm4(al[i], su32(&Al[ar * GS + kk + a_k]));
            }
#pragma unroll
            for (int np = 0; np < 4; np++) {
                int br = wn + np * 16 + b_n;
                uint32_t bh[4], bl[4];
                ldsm4(bh, su32(&Bh[br * GS + kk + b_k]));
                ldsm4(bl, su32(&Bl[br * GS + kk + b_k]));
#pragma unroll
                for (int i = 0; i < 2; i++) {
                    mma16816(acc[i][np * 2],     ah[i], bh[0], bh[2]);
                    mma16816(acc[i][np * 2 + 1], ah[i], bh[1], bh[3]);
                    mma16816(acc[i][np * 2],     ah[i], bl[0], bl[2]);
                    mma16816(acc[i][np * 2 + 1], ah[i], bl[1], bl[3]);
                    mma16816(acc[i][np * 2],     al[i], bh[0], bh[2]);
                    mma16816(acc[i][np * 2 + 1], al[i], bh[1], bh[3]);
                }
            }
        }
        __syncthreads();
    }

    const int tr = lane >> 2;
    const int tc = (lane & 3) * 2;
#pragma unroll
    for (int i = 0; i < 2; i++) {
#pragma unroll
        for (int n = 0; n < 8; n++) {
            int col = bn + wn + n * 8 + tc;
            float bb0 = bias ? bias[col]     : 0.f;
            float bb1 = bias ? bias[col + 1] : 0.f;
            int row0 = bm + wm + i * 16 + tr;
            float2 v0 = make_float2(acc[i][n][0] + bb0, acc[i][n][1] + bb1);
            float2 v1 = make_float2(acc[i][n][2] + bb0, acc[i][n][3] + bb1);
            *(float2*)&C[(size_t)row0 * N + col]       = v0;
            *(float2*)&C[(size_t)(row0 + 8) * N + col] = v1;
        }
    }
}

// ---------------------------------------------------------------------------
// RoPE (fp32, unchanged)
// ---------------------------------------------------------------------------
__global__ void rope_table_kernel(const int* __restrict__ pos,
                                  float* __restrict__ ct, float* __restrict__ st)
{
    int idx = blockIdx.x * blockDim.x + threadIdx.x;
    if (idx >= T_SEQ * (HD / 2)) return;
    int d = idx & 63;
    int t = idx >> 6;
    double inv = exp(-((double)(2 * d) / (double)HD) * 9.210340371976184);
    double ang = (double)pos[t] * inv;
    ct[idx] = (float)cos(ang);
    st[idx] = (float)sin(ang);
}

__global__ void rope_apply_kernel(float* __restrict__ qkv,
                                  const float* __restrict__ ct,
                                  const float* __restrict__ st)
{
    int idx = blockIdx.x * blockDim.x + threadIdx.x;
    if (idx >= T_SEQ * (NH + NKV) * 64) return;
    int d = idx & 63;
    int h = (idx >> 6) % (NH + NKV);
    int t = idx / ((NH + NKV) * 64);
    float* base = qkv + (size_t)t * QKV_N + h * HD;
    float c = ct[t * 64 + d], s = st[t * 64 + d];
    float x1 = base[d], x2 = base[d + 64];
    base[d]      = x1 * c - x2 * s;
    base[d + 64] = x2 * c + x1 * s;
}

// ===========================================================================
// HMMA flash attention. Q-tile 128 x K-tile 64, 8 warps (16 q-rows each).
// 3-term hi/lo for both S=QK^T and O=PV. Softmax in registers (exp2 domain,
// scale*log2e pre-folded into Q). Output written as bf16 hi/lo.
// smem (bf16 units, stride 136): Qh,Ql 128x136 each; 2 KV buffers of
// {Kh,Kl,Vh,Vl} 64x136 each.
// ===========================================================================
#define SKS 136
#define AT_QSZ   (128 * SKS)               // per Q matrix
#define AT_KSZ   (64 * SKS)                // per K/V matrix
#define AT_BUF   (4 * AT_KSZ)              // one KV stage
#define AT_SMEM  ((2 * AT_QSZ + 2 * AT_BUF) * 2)   // bytes = 208896

__global__ void __launch_bounds__(256, 1)
attn_mma(const __nv_bfloat16* __restrict__ qkvh,
         const __nv_bfloat16* __restrict__ qkvl,
         __nv_bfloat16* __restrict__ outh,
         __nv_bfloat16* __restrict__ outl)
{
    extern __shared__ __nv_bfloat16 sma[];
    __nv_bfloat16* Qh = sma;
    __nv_bfloat16* Ql = sma + AT_QSZ;
    __nv_bfloat16* KV = sma + 2 * AT_QSZ;

    const int tid = threadIdx.x, wid = tid >> 5, lane = tid & 31;
    const int h = blockIdx.y;
    const int qt = (int)gridDim.x - 1 - (int)blockIdx.x;   // heavy tiles first
    const int qbase = qt * 128;
    const int g = h >> 3;                                  // h / GQA
    const int qoff = h * HD;
    const int koff = NH * HD + g * HD;                     // 2048 + g*128
    const int voff = (NH + NKV) * HD + g * HD;             // 2304 + g*128

    // ---- load Q tile (plain loads) ----
#pragma unroll
    for (int i = 0; i < 16; i++) {
        int c = tid + i * 256;            // 4096 chunks of 16B
        int hl = c >> 11;
        int w = c & 2047;
        int row = w >> 4, cc = w & 15;
        const __nv_bfloat16* src = (hl ? qkvl : qkvh)
            + (size_t)(qbase + row) * QKV_N + qoff + cc * 8;
        __nv_bfloat16* dst = (hl ? Ql : Qh) + row * SKS + cc * 8;
        *(uint4*)dst = *(const uint4*)src;
    }

    auto load_kv = [&](int buf, int kt) {
        const int kbase = kt * 64;
        __nv_bfloat16* base = KV + buf * AT_BUF;
#pragma unroll
        for (int i = 0; i < 16; i++) {
            int c = tid + i * 256;        // 4096 chunks of 16B
            int mat = c >> 10;            // 0 Kh, 1 Kl, 2 Vh, 3 Vl
            int w = c & 1023;
            int row = w >> 4, cc = w & 15;
            const __nv_bfloat16* src = ((mat & 1) ? qkvl : qkvh)
                + (size_t)(kbase + row) * QKV_N + ((mat >> 1) ? voff : koff) + cc * 8;
            cp_async16(su32(base + mat * AT_KSZ + row * SKS + cc * 8), src);
        }
    };

    const int nkt = 2 * qt + 2;
    load_kv(0, 0); CP_COMMIT();

    float o[16][4];
#pragma unroll
    for (int d = 0; d < 16; d++)
#pragma unroll
        for (int e = 0; e < 4; e++) o[d][e] = 0.f;
    float m0 = -1e30f, m1 = -1e30f, l0 = 0.f, l1 = 0.f;

    const int wq = wid * 16;
    const int a_r = lane & 15, a_k = (lane >> 4) * 8;
    const int b_n = ((lane >> 3) & 1) * 8 + (lane & 7), b_k = (lane >> 4) * 8;

    for (int kt = 0; kt < nkt; kt++) {
        if (kt + 1 < nkt) { load_kv((kt + 1) & 1, kt + 1); CP_COMMIT(); CP_WAIT1(); }
        else CP_WAIT0();
        __syncthreads();

        __nv_bfloat16* Kh = KV + (kt & 1) * AT_BUF;
        __nv_bfloat16* Kl = Kh + AT_KSZ;
        __nv_bfloat16* Vh = Kl + AT_KSZ;
        __nv_bfloat16* Vl = Vh + AT_KSZ;

        // ---- S = Q @ K^T (3 terms) ----
        float s[8][4];
#pragma unroll
        for (int n = 0; n < 8; n++)
#pragma unroll
            for (int e = 0; e < 4; e++) s[n][e] = 0.f;

#pragma unroll
        for (int kk = 0; kk < 128; kk += 16) {
            uint32_t qh4[4], ql4[4];
            int qr = wq + a_r;
            ldsm4(qh4, su32(&Qh[qr * SKS + kk + a_k]));
            ldsm4(ql4, su32(&Ql[qr * SKS + kk + a_k]));
#pragma unroll
            for (int g4 = 0; g4 < 4; g4++) {
                int br = g4 * 16 + b_n;
                uint32_t bh[4], bl[4];
                ldsm4(bh, su32(&Kh[br * SKS + kk + b_k]));
                ldsm4(bl, su32(&Kl[br * SKS + kk + b_k]));
                mma16816(s[g4 * 2],     qh4, bh[0], bh[2]);
                mma16816(s[g4 * 2 + 1], qh4, bh[1], bh[3]);
                mma16816(s[g4 * 2],     qh4, bl[0], bl[2]);
                mma16816(s[g4 * 2 + 1], qh4, bl[1], bl[3]);
                mma16816(s[g4 * 2],     ql4, bh[0], bh[2]);
                mma16816(s[g4 * 2 + 1], ql4, bh[1], bh[3]);
            }
        }

        // ---- causal mask (only last two k-tiles can touch the diagonal) ----
        const int kbase = kt * 64;
        if (kt >= 2 * qt) {
            int rg0 = qbase + wq + (lane >> 2);
#pragma unroll
            for (int n = 0; n < 8; n++) {
                int cg = kbase + n * 8 + (lane & 3) * 2;
                if (cg > rg0)         s[n][0] = -1e30f;
                if (cg + 1 > rg0)     s[n][1] = -1e30f;
                if (cg > rg0 + 8)     s[n][2] = -1e30f;
                if (cg + 1 > rg0 + 8) s[n][3] = -1e30f;
            }
        }

        // ---- online softmax (exp2 domain; rows r0 = lane>>2, r0+8) ----
        float mx0 = -1e30f, mx1 = -1e30f;
#pragma unroll
        for (int n = 0; n < 8; n++) {
            mx0 = fmaxf(mx0, fmaxf(s[n][0], s[n][1]));
            mx1 = fmaxf(mx1, fmaxf(s[n][2], s[n][3]));
        }
        mx0 = fmaxf(mx0, __shfl_xor_sync(0xffffffffu, mx0, 1));
        mx0 = fmaxf(mx0, __shfl_xor_sync(0xffffffffu, mx0, 2));
        mx1 = fmaxf(mx1, __shfl_xor_sync(0xffffffffu, mx1, 1));
        mx1 = fmaxf(mx1, __shfl_xor_sync(0xffffffffu, mx1, 2));
        float mn0 = fmaxf(m0, mx0), mn1 = fmaxf(m1, mx1);
        float c0 = ex2f(m0 - mn0), c1 = ex2f(m1 - mn1);
        float rs0 = 0.f, rs1 = 0.f;
#pragma unroll
        for (int n = 0; n < 8; n++) {
            s[n][0] = ex2f(s[n][0] - mn0); rs0 += s[n][0];
            s[n][1] = ex2f(s[n][1] - mn0); rs0 += s[n][1];
            s[n][2] = ex2f(s[n][2] - mn1); rs1 += s[n][2];
            s[n][3] = ex2f(s[n][3] - mn1); rs1 += s[n][3];
        }
        rs0 += __shfl_xor_sync(0xffffffffu, rs0, 1);
        rs0 += __shfl_xor_sync(0xffffffffu, rs0, 2);
        rs1 += __shfl_xor_sync(0xffffffffu, rs1, 1);
        rs1 += __shfl_xor_sync(0xffffffffu, rs1, 2);
        l0 = l0 * c0 + rs0; l1 = l1 * c1 + rs1;
        m0 = mn0; m1 = mn1;
#pragma unroll
        for (int d = 0; d < 16; d++) {
            o[d][0] *= c0; o[d][1] *= c0;
            o[d][2] *= c1; o[d][3] *= c1;
        }

        // ---- build P fragments (A-layout) from S (C-layout), hi/lo split ----
        uint32_t aPh[4][4], aPl[4][4];
#pragma unroll
        for (int kb = 0; kb < 4; kb++) {
            float* f0 = s[2 * kb];
            float* f1 = s[2 * kb + 1];
            aPh[kb][0] = packbf(f0[0], f0[1]);
            aPh[kb][1] = packbf(f0[2], f0[3]);
            aPh[kb][2] = packbf(f1[0], f1[1]);
            aPh[kb][3] = packbf(f1[2], f1[3]);
            __nv_bfloat162* hp;
            hp = (__nv_bfloat162*)&aPh[kb][0];
            aPl[kb][0] = packbf(f0[0] - __bfloat162float(hp->x), f0[1] - __bfloat162float(hp->y));
            hp = (__nv_bfloat162*)&aPh[kb][1];
            aPl[kb][1] = packbf(f0[2] - __bfloat162float(hp->x), f0[3] - __bfloat162float(hp->y));
            hp = (__nv_bfloat162*)&aPh[kb][2];
            aPl[kb][2] = packbf(f1[0] - __bfloat162float(hp->x), f1[1] - __bfloat162float(hp->y));
            hp = (__nv_bfloat162*)&aPh[kb][3];
            aPl[kb][3] = packbf(f1[2] - __bfloat162float(hp->x), f1[3] - __bfloat162float(hp->y));
        }

        // ---- O += P @ V (3 terms), V via ldmatrix.trans ----
#pragma unroll
        for (int kb = 0; kb < 4; kb++) {
            int vr = kb * 16 + b_n;
#pragma unroll
            for (int dg = 0; dg < 8; dg++) {
                uint32_t vh4[4], vl4[4];
                ldsm4t(vh4, su32(&Vh[vr * SKS + dg * 16 + b_k]));
                ldsm4t(vl4, su32(&Vl[vr * SKS + dg * 16 + b_k]));
                mma16816(o[dg * 2],     aPh[kb], vh4[0], vh4[1]);
                mma16816(o[dg * 2 + 1], aPh[kb], vh4[2], vh4[3]);
                mma16816(o[dg * 2],     aPh[kb], vl4[0], vl4[1]);
                mma16816(o[dg * 2 + 1], aPh[kb], vl4[2], vl4[3]);
                mma16816(o[dg * 2],     aPl[kb], vh4[0], vh4[1]);
                mma16816(o[dg * 2 + 1], aPl[kb], vh4[2], vh4[3]);
            }
        }
        __syncthreads();
    }

    // ---- epilogue: O/l, write bf16 hi/lo ----
    float inv0 = 1.f / l0, inv1 = 1.f / l1;
    int row0 = qbase + wq + (lane >> 2);
    int colb = h * HD + (lane & 3) * 2;
#pragma unroll
    for (int dg = 0; dg < 16; dg++) {
        int col = colb + dg * 8;
        float v00 = o[dg][0] * inv0, v01 = o[dg][1] * inv0;
        float v10 = o[dg][2] * inv1, v11 = o[dg][3] * inv1;
        __nv_bfloat162 hA = __floats2bfloat162_rn(v00, v01);
        __nv_bfloat162 hB = __floats2bfloat162_rn(v10, v11);
        __nv_bfloat162 lA = __floats2bfloat162_rn(v00 - __bfloat162float(hA.x),
                                                  v01 - __bfloat162float(hA.y));
        __nv_bfloat162 lB = __floats2bfloat162_rn(v10 - __bfloat162float(hB.x),
                                                  v11 - __bfloat162float(hB.y));
        *(__nv_bfloat162*)(outh + (size_t)row0 * HID + col)       = hA;
        *(__nv_bfloat162*)(outl + (size_t)row0 * HID + col)       = lA;
        *(__nv_bfloat162*)(outh + (size_t)(row0 + 8) * HID + col) = hB;
        *(__nv_bfloat162*)(outl + (size_t)(row0 + 8) * HID + col) = lB;
    }
}

// ---------------------------------------------------------------------------
extern "C" void kernel_launch(void* const* d_in, const int* in_sizes, int n_in,
                              void* d_out, int out_size)
{
    const int*   positions = (const int*)d_in[0];
    const float* hidden    = (const float*)d_in[1];
    const float* w_qkv     = (const float*)d_in[2];
    const float* b_qkv     = (const float*)d_in[3];
    const float* w_o       = (const float*)d_in[4];
    float* out = (float*)d_out;

    float *qkv, *ct, *st;
    __nv_bfloat16 *hidh, *hidl, *wqh, *wql, *woh, *wol, *qkvh, *qkvl, *ath, *atl;
    cudaGetSymbolAddress((void**)&qkv,  g_qkv);
    cudaGetSymbolAddress((void**)&ct,   g_cos);
    cudaGetSymbolAddress((void**)&st,   g_sin);
    cudaGetSymbolAddress((void**)&hidh, g_hidh);
    cudaGetSymbolAddress((void**)&hidl, g_hidl);
    cudaGetSymbolAddress((void**)&wqh,  g_wqh);
    cudaGetSymbolAddress((void**)&wql,  g_wql);
    cudaGetSymbolAddress((void**)&woh,  g_woh);
    cudaGetSymbolAddress((void**)&wol,  g_wol);
    cudaGetSymbolAddress((void**)&qkvh, g_qkvh);
    cudaGetSymbolAddress((void**)&qkvl, g_qkvl);
    cudaGetSymbolAddress((void**)&ath,  g_attnh);
    cudaGetSymbolAddress((void**)&atl,  g_attnl);

    cudaFuncSetAttribute(gemm_bf,
                         cudaFuncAttributeMaxDynamicSharedMemorySize, GB_SMEM);
    cudaFuncSetAttribute(attn_mma,
                         cudaFuncAttributeMaxDynamicSharedMemorySize, AT_SMEM);

    // 0) split inputs to bf16 hi/lo
    {
        int n1 = T_SEQ * HID;
        split_plain<<<n1 / 1024, 256>>>(hidden, hidh, hidl, n1);
        int n2 = QKV_N * HID;
        split_plain<<<n2 / 1024, 256>>>(w_qkv, wqh, wql, n2);
        int n3 = HID * HID;
        split_plain<<<n3 / 1024, 256>>>(w_o, woh, wol, n3);
    }

    // 1) qkv = hidden @ w_qkv^T + b_qkv
    dim3 g1(QKV_N / 128, T_SEQ / 128);
    gemm_bf<<<g1, 256, GB_SMEM>>>(hidh, hidl, wqh, wql, b_qkv, qkv,
                                  T_SEQ, QKV_N, HID);

    // 2) RoPE (fp32)
    int nt = T_SEQ * (HD / 2);
    rope_table_kernel<<<(nt + 255) / 256, 256>>>(positions, ct, st);
    int na = T_SEQ * (NH + NKV) * 64;
    rope_apply_kernel<<<(na + 255) / 256, 256>>>(qkv, ct, st);

    // 3) split qkv (q scaled by 1/sqrt(HD)*log2e)
    int nq = T_SEQ * QKV_N;
    split_qkv_kernel<<<nq / 1024, 256>>>(qkv, qkvh, qkvl);

    // 4) flash attention (HMMA), writes bf16 hi/lo attn output
    attn_mma<<<dim3(T_SEQ / 128, NH), 256, AT_SMEM>>>(qkvh, qkvl, ath, atl);

    // 5) out = attn @ w_o^T
    dim3 g2(HID / 128, T_SEQ / 128);
    gemm_bf<<<g2, 256, GB_SMEM>>>(ath, atl, woh, wol, nullptr, out,
                                  T_SEQ, HID, HID);
}

// round 5
// speedup vs baseline: 5.0952x; 1.1641x over previous
#include <cuda_runtime.h>
#include <cuda_bf16.h>
#include <cuda_fp16.h>
#include <math.h>
#include <stdint.h>

#define T_SEQ 4096
#define HID   2048
#define NH    16
#define NKV   2
#define HD    128
#define QKV_N ((NH + 2*NKV)*HD)   // 2560
#define GQA   (NH/NKV)            // 8

// ---------------------------------------------------------------------------
// Device-global scratch
// ---------------------------------------------------------------------------
__device__ float g_qkv[4096 * 2560];                 // fp32 qkv (pre-RoPE)
__device__ __nv_bfloat16 g_hidh[4096 * 2048], g_hidl[4096 * 2048];
__device__ __nv_bfloat16 g_wqh[2560 * 2048],  g_wql[2560 * 2048];
__device__ __nv_bfloat16 g_woh[2048 * 2048],  g_wol[2048 * 2048];
__device__ __half        g_qkvh[4096 * 2560], g_qkvl[4096 * 2560];
__device__ __nv_bfloat16 g_attnh[4096 * 2048], g_attnl[4096 * 2048];
__device__ float g_cos[4096 * 64];
__device__ float g_sin[4096 * 64];

// ---------------------------------------------------------------------------
// Helpers
// ---------------------------------------------------------------------------
__device__ __forceinline__ uint32_t su32(const void* p) {
    uint32_t a;
    asm("{ .reg .u64 t; cvta.to.shared.u64 t, %1; cvt.u32.u64 %0, t; }"
        : "=r"(a) : "l"(p));
    return a;
}
__device__ __forceinline__ void ldsm4(uint32_t* r, uint32_t addr) {
    asm volatile("ldmatrix.sync.aligned.m8n8.x4.shared.b16 {%0,%1,%2,%3}, [%4];"
                 : "=r"(r[0]), "=r"(r[1]), "=r"(r[2]), "=r"(r[3]) : "r"(addr));
}
__device__ __forceinline__ void ldsm4t(uint32_t* r, uint32_t addr) {
    asm volatile("ldmatrix.sync.aligned.m8n8.x4.trans.shared.b16 {%0,%1,%2,%3}, [%4];"
                 : "=r"(r[0]), "=r"(r[1]), "=r"(r[2]), "=r"(r[3]) : "r"(addr));
}
__device__ __forceinline__ void mma16816(float* c, const uint32_t* a,
                                         uint32_t b0, uint32_t b1) {
    asm volatile(
        "mma.sync.aligned.m16n8k16.row.col.f32.bf16.bf16.f32 "
        "{%0,%1,%2,%3}, {%4,%5,%6,%7}, {%8,%9}, {%0,%1,%2,%3};"
        : "+f"(c[0]), "+f"(c[1]), "+f"(c[2]), "+f"(c[3])
        : "r"(a[0]), "r"(a[1]), "r"(a[2]), "r"(a[3]), "r"(b0), "r"(b1));
}
__device__ __forceinline__ void mma16816h(float* c, const uint32_t* a,
                                          uint32_t b0, uint32_t b1) {
    asm volatile(
        "mma.sync.aligned.m16n8k16.row.col.f32.f16.f16.f32 "
        "{%0,%1,%2,%3}, {%4,%5,%6,%7}, {%8,%9}, {%0,%1,%2,%3};"
        : "+f"(c[0]), "+f"(c[1]), "+f"(c[2]), "+f"(c[3])
        : "r"(a[0]), "r"(a[1]), "r"(a[2]), "r"(a[3]), "r"(b0), "r"(b1));
}
__device__ __forceinline__ void cp_async8(uint32_t smem, const void* g) {
    asm volatile("cp.async.ca.shared.global [%0], [%1], 8;" :: "r"(smem), "l"(g));
}
__device__ __forceinline__ void cp_async16(uint32_t smem, const void* g) {
    asm volatile("cp.async.cg.shared.global [%0], [%1], 16;" :: "r"(smem), "l"(g));
}
#define CP_COMMIT() asm volatile("cp.async.commit_group;" ::: "memory")
#define CP_WAIT0()  asm volatile("cp.async.wait_group 0;" ::: "memory")
#define CP_WAIT1()  asm volatile("cp.async.wait_group 1;" ::: "memory")

__device__ __forceinline__ float ex2f(float x) {
    float y;
    asm("ex2.approx.ftz.f32 %0, %1;" : "=f"(y) : "f"(x));
    return y;
}
__device__ __forceinline__ uint32_t packh(float x, float y) {
    __half2 t = __floats2half2_rn(x, y);
    return *(uint32_t*)&t;
}

// ---------------------------------------------------------------------------
// Split kernels
// ---------------------------------------------------------------------------
__device__ __forceinline__ void split4bf(float4 v, __nv_bfloat16* hi, __nv_bfloat16* lo) {
    __nv_bfloat16 h0 = __float2bfloat16_rn(v.x), h1 = __float2bfloat16_rn(v.y);
    __nv_bfloat16 h2 = __float2bfloat16_rn(v.z), h3 = __float2bfloat16_rn(v.w);
    uint64_t wh = (uint64_t)__bfloat16_as_ushort(h0)
                | ((uint64_t)__bfloat16_as_ushort(h1) << 16)
                | ((uint64_t)__bfloat16_as_ushort(h2) << 32)
                | ((uint64_t)__bfloat16_as_ushort(h3) << 48);
    __nv_bfloat16 l0 = __float2bfloat16_rn(v.x - __bfloat162float(h0));
    __nv_bfloat16 l1 = __float2bfloat16_rn(v.y - __bfloat162float(h1));
    __nv_bfloat16 l2 = __float2bfloat16_rn(v.z - __bfloat162float(h2));
    __nv_bfloat16 l3 = __float2bfloat16_rn(v.w - __bfloat162float(h3));
    uint64_t wl = (uint64_t)__bfloat16_as_ushort(l0)
                | ((uint64_t)__bfloat16_as_ushort(l1) << 16)
                | ((uint64_t)__bfloat16_as_ushort(l2) << 32)
                | ((uint64_t)__bfloat16_as_ushort(l3) << 48);
    *(uint64_t*)hi = wh;
    *(uint64_t*)lo = wl;
}
__device__ __forceinline__ void split4h(float4 v, __half* hi, __half* lo) {
    __half h0 = __float2half_rn(v.x), h1 = __float2half_rn(v.y);
    __half h2 = __float2half_rn(v.z), h3 = __float2half_rn(v.w);
    uint64_t wh = (uint64_t)__half_as_ushort(h0)
                | ((uint64_t)__half_as_ushort(h1) << 16)
                | ((uint64_t)__half_as_ushort(h2) << 32)
                | ((uint64_t)__half_as_ushort(h3) << 48);
    __half l0 = __float2half_rn(v.x - __half2float(h0));
    __half l1 = __float2half_rn(v.y - __half2float(h1));
    __half l2 = __float2half_rn(v.z - __half2float(h2));
    __half l3 = __float2half_rn(v.w - __half2float(h3));
    uint64_t wl = (uint64_t)__half_as_ushort(l0)
                | ((uint64_t)__half_as_ushort(l1) << 16)
                | ((uint64_t)__half_as_ushort(l2) << 32)
                | ((uint64_t)__half_as_ushort(l3) << 48);
    *(uint64_t*)hi = wh;
    *(uint64_t*)lo = wl;
}

__global__ void split_plain(const float* __restrict__ in,
                            __nv_bfloat16* __restrict__ hi,
                            __nv_bfloat16* __restrict__ lo, int n)
{
    int i = (blockIdx.x * blockDim.x + threadIdx.x) * 4;
    if (i >= n) return;
    split4bf(*(const float4*)(in + i), hi + i, lo + i);
}

// ---------------------------------------------------------------------------
// RoPE table + fused rope+fp16 split for q/k; separate fp16 split for v
// ---------------------------------------------------------------------------
__global__ void rope_table_kernel(const int* __restrict__ pos,
                                  float* __restrict__ ct, float* __restrict__ st)
{
    int idx = blockIdx.x * blockDim.x + threadIdx.x;
    if (idx >= T_SEQ * (HD / 2)) return;
    int d = idx & 63;
    int t = idx >> 6;
    double inv = exp(-((double)(2 * d) / (double)HD) * 9.210340371976184);
    double ang = (double)pos[t] * inv;
    ct[idx] = (float)cos(ang);
    st[idx] = (float)sin(ang);
}

#define QSC (0.08838834764831845f * 1.4426950408889634f)  // 1/sqrt(HD) * log2(e)

__global__ void rope_split_kernel(const float* __restrict__ qkv,
                                  const float* __restrict__ ct,
                                  const float* __restrict__ st,
                                  __half* __restrict__ oh, __half* __restrict__ ol)
{
    int idx = blockIdx.x * blockDim.x + threadIdx.x;
    if (idx >= T_SEQ * (NH + NKV) * 16) return;
    int c16 = idx & 15;
    int h = (idx >> 4) % (NH + NKV);
    int t = idx / ((NH + NKV) * 16);
    int d = c16 * 4;
    const float* base = qkv + (size_t)t * QKV_N + h * HD;
    float4 x1 = *(const float4*)(base + d);
    float4 x2 = *(const float4*)(base + d + 64);
    float4 c = *(const float4*)(ct + t * 64 + d);
    float4 s = *(const float4*)(st + t * 64 + d);
    float4 y1, y2;
    y1.x = x1.x * c.x - x2.x * s.x;  y2.x = x2.x * c.x + x1.x * s.x;
    y1.y = x1.y * c.y - x2.y * s.y;  y2.y = x2.y * c.y + x1.y * s.y;
    y1.z = x1.z * c.z - x2.z * s.z;  y2.z = x2.z * c.z + x1.z * s.z;
    y1.w = x1.w * c.w - x2.w * s.w;  y2.w = x2.w * c.w + x1.w * s.w;
    if (h < NH) {
        y1.x *= QSC; y1.y *= QSC; y1.z *= QSC; y1.w *= QSC;
        y2.x *= QSC; y2.y *= QSC; y2.z *= QSC; y2.w *= QSC;
    }
    size_t o = (size_t)t * QKV_N + h * HD + d;
    split4h(y1, oh + o,      ol + o);
    split4h(y2, oh + o + 64, ol + o + 64);
}

__global__ void split_v_kernel(const float* __restrict__ qkv,
                               __half* __restrict__ oh, __half* __restrict__ ol)
{
    int idx = blockIdx.x * blockDim.x + threadIdx.x;
    if (idx >= T_SEQ * 64) return;        // 256 v cols / 4
    int t = idx >> 6;
    int c = (idx & 63) * 4 + (NH + NKV) * HD;
    size_t o = (size_t)t * QKV_N + c;
    split4h(*(const float4*)(qkv + o), oh + o, ol + o);
}

// ===========================================================================
// bf16 hi/lo GEMM (3-term), 128x128 tile, BK=32, 8 warps, cp.async 2-stage.
// Term-reordered MMAs (dependent accumulator reuse at distance 4), hoisted
// smem addresses.
// ===========================================================================
#define GS 40
#define MATB (128 * GS * 2)                 // bytes per matrix per stage
#define GB_STAGE (4 * 128 * GS)             // half units per stage
#define GB_SMEM  (2 * GB_STAGE * 2)         // 81920 bytes

__global__ void __launch_bounds__(256, 2)
gemm_bf(const __nv_bfloat16* __restrict__ Ah_g, const __nv_bfloat16* __restrict__ Al_g,
        const __nv_bfloat16* __restrict__ Bh_g, const __nv_bfloat16* __restrict__ Bl_g,
        const float* __restrict__ bias, float* __restrict__ C,
        int M, int N, int K)
{
    extern __shared__ __nv_bfloat16 smg[];
    const int tid = threadIdx.x, wid = tid >> 5, lane = tid & 31;
    const int bm = blockIdx.y * 128, bn = blockIdx.x * 128;
    const int wm = (wid & 3) * 32, wn = (wid >> 2) * 64;

    float acc[2][8][4];
#pragma unroll
    for (int i = 0; i < 2; i++)
#pragma unroll
        for (int n = 0; n < 8; n++)
#pragma unroll
            for (int e = 0; e < 4; e++) acc[i][n][e] = 0.f;

    const int S = K / 32;

    auto issue = [&](int buf, int s) {
        __nv_bfloat16* base = smg + buf * GB_STAGE;
        const int k0 = s * 32;
#pragma unroll
        for (int i = 0; i < 16; i++) {
            int c = tid + i * 256;
            int mat = c >> 10;
            int w = c & 1023;
            int row = w >> 3, cc = w & 7;
            const __nv_bfloat16* src =
                (mat == 0) ? Ah_g + (size_t)(bm + row) * K + k0 + cc * 4 :
                (mat == 1) ? Al_g + (size_t)(bm + row) * K + k0 + cc * 4 :
                (mat == 2) ? Bh_g + (size_t)(bn + row) * K + k0 + cc * 4 :
                             Bl_g + (size_t)(bn + row) * K + k0 + cc * 4;
            cp_async8(su32(base + mat * (128 * GS) + row * GS + cc * 4), src);
        }
    };

    issue(0, 0); CP_COMMIT();

    const int a_r = lane & 15, a_k = (lane >> 4) * 8;
    const int b_n = ((lane >> 3) & 1) * 8 + (lane & 7), b_k = (lane >> 4) * 8;
    const uint32_t smb = su32(smg);
    const uint32_t a_base = 2 * ((wm + a_r) * GS + a_k);
    const uint32_t b_base = 2 * ((wn + b_n) * GS + b_k);

    for (int s = 0; s < S; s++) {
        if (s + 1 < S) { issue((s + 1) & 1, s + 1); CP_COMMIT(); CP_WAIT1(); }
        else CP_WAIT0();
        __syncthreads();

        const uint32_t stb = smb + (s & 1) * (GB_STAGE * 2);
        const uint32_t pAh = stb + a_base;
        const uint32_t pAl = pAh + MATB;
        const uint32_t pBh = stb + 2 * MATB + b_base;
        const uint32_t pBl = pBh + MATB;

#pragma unroll
        for (int kk = 0; kk < 2; kk++) {
            const uint32_t ko = kk * 32;
            uint32_t ah[2][4], al[2][4];
            ldsm4(ah[0], pAh + ko);
            ldsm4(ah[1], pAh + ko + 16 * GS * 2);
            ldsm4(al[0], pAl + ko);
            ldsm4(al[1], pAl + ko + 16 * GS * 2);
#pragma unroll
            for (int np = 0; np < 4; np++) {
                uint32_t bh[4], bl[4];
                ldsm4(bh, pBh + ko + np * (16 * GS * 2));
                ldsm4(bl, pBl + ko + np * (16 * GS * 2));
                mma16816(acc[0][np * 2],     ah[0], bh[0], bh[2]);
                mma16816(acc[0][np * 2 + 1], ah[0], bh[1], bh[3]);
                mma16816(acc[1][np * 2],     ah[1], bh[0], bh[2]);
                mma16816(acc[1][np * 2 + 1], ah[1], bh[1], bh[3]);
                mma16816(acc[0][np * 2],     ah[0], bl[0], bl[2]);
                mma16816(acc[0][np * 2 + 1], ah[0], bl[1], bl[3]);
                mma16816(acc[1][np * 2],     ah[1], bl[0], bl[2]);
                mma16816(acc[1][np * 2 + 1], ah[1], bl[1], bl[3]);
                mma16816(acc[0][np * 2],     al[0], bh[0], bh[2]);
                mma16816(acc[0][np * 2 + 1], al[0], bh[1], bh[3]);
                mma16816(acc[1][np * 2],     al[1], bh[0], bh[2]);
                mma16816(acc[1][np * 2 + 1], al[1], bh[1], bh[3]);
            }
        }
        __syncthreads();
    }

    const int tr = lane >> 2;
    const int tc = (lane & 3) * 2;
#pragma unroll
    for (int i = 0; i < 2; i++) {
#pragma unroll
        for (int n = 0; n < 8; n++) {
            int col = bn + wn + n * 8 + tc;
            float bb0 = bias ? bias[col]     : 0.f;
            float bb1 = bias ? bias[col + 1] : 0.f;
            int row0 = bm + wm + i * 16 + tr;
            float2 v0 = make_float2(acc[i][n][0] + bb0, acc[i][n][1] + bb1);
            float2 v1 = make_float2(acc[i][n][2] + bb0, acc[i][n][3] + bb1);
            *(float2*)&C[(size_t)row0 * N + col]       = v0;
            *(float2*)&C[(size_t)(row0 + 8) * N + col] = v1;
        }
    }
}

// ===========================================================================
// fp16 HMMA flash attention. Q single fp16 (pre-scaled by QSC), K hi/lo,
// V hi/lo, P single fp16. S = Qh(Kh+Kl) [2 terms], PV = Ph(Vh+Vl) [2 terms].
// Q-tile 128 x K-tile 64, 8 warps, cp.async double-buffered KV.
// ===========================================================================
#define SKS 136
#define AT_QSZ (128 * SKS)                  // halves
#define AT_KSZ (64 * SKS)                   // halves per matrix
#define KMATB  (AT_KSZ * 2)                 // bytes per matrix
#define AT_STAGEB (4 * KMATB)               // bytes per KV stage
#define AT_SMEM (AT_QSZ * 2 + 2 * AT_STAGEB)  // 34816 + 139264 = 174080 bytes

__global__ void __launch_bounds__(256, 1)
attn_mma(const __half* __restrict__ qkvh,
         const __half* __restrict__ qkvl,
         __nv_bfloat16* __restrict__ outh,
         __nv_bfloat16* __restrict__ outl)
{
    extern __shared__ __half sma[];
    __half* Qs = sma;
    __half* KV = sma + AT_QSZ;

    const int tid = threadIdx.x, wid = tid >> 5, lane = tid & 31;
    const int h = blockIdx.y;
    const int qt = (int)gridDim.x - 1 - (int)blockIdx.x;   // heavy tiles first
    const int qbase = qt * 128;
    const int g = h >> 3;
    const int qoff = h * HD;
    const int koff = NH * HD + g * HD;
    const int voff = (NH + NKV) * HD + g * HD;

    // ---- load Q tile (single fp16) ----
#pragma unroll
    for (int i = 0; i < 8; i++) {
        int c = tid + i * 256;            // 2048 chunks of 16B
        int row = c >> 4, cc = c & 15;
        const __half* src = qkvh + (size_t)(qbase + row) * QKV_N + qoff + cc * 8;
        *(uint4*)(Qs + row * SKS + cc * 8) = *(const uint4*)src;
    }

    auto load_kv = [&](int buf, int kt) {
        const int kbase = kt * 64;
        __half* base = KV + buf * (4 * AT_KSZ);
#pragma unroll
        for (int i = 0; i < 16; i++) {
            int c = tid + i * 256;        // 4096 chunks
            int mat = c >> 10;            // 0 Kh, 1 Kl, 2 Vh, 3 Vl
            int w = c & 1023;
            int row = w >> 4, cc = w & 15;
            const __half* src = ((mat & 1) ? qkvl : qkvh)
                + (size_t)(kbase + row) * QKV_N + ((mat >> 1) ? voff : koff) + cc * 8;
            cp_async16(su32(base + mat * AT_KSZ + row * SKS + cc * 8), src);
        }
    };

    const int nkt = 2 * qt + 2;
    load_kv(0, 0); CP_COMMIT();

    float o[16][4];
#pragma unroll
    for (int d = 0; d < 16; d++)
#pragma unroll
        for (int e = 0; e < 4; e++) o[d][e] = 0.f;
    float m0 = -1e30f, m1 = -1e30f, l0 = 0.f, l1 = 0.f;

    const int wq = wid * 16;
    const int a_r = lane & 15, a_k = (lane >> 4) * 8;
    const int b_n = ((lane >> 3) & 1) * 8 + (lane & 7), b_k = (lane >> 4) * 8;

    const uint32_t smb = su32(sma);
    const uint32_t pQ = smb + 2 * ((wq + a_r) * SKS + a_k);
    const uint32_t bk_base = 2 * (b_n * SKS + b_k);

    for (int kt = 0; kt < nkt; kt++) {
        if (kt + 1 < nkt) { load_kv((kt + 1) & 1, kt + 1); CP_COMMIT(); CP_WAIT1(); }
        else CP_WAIT0();
        __syncthreads();

        const uint32_t kvb = smb + AT_QSZ * 2 + (kt & 1) * AT_STAGEB;
        const uint32_t pK = kvb + bk_base;                    // Kh; Kl at +KMATB
        const uint32_t pV = kvb + 2 * KMATB + bk_base;        // Vh; Vl at +KMATB

        // ---- S = Qh @ (Kh + Kl)^T ----
        float s[8][4];
#pragma unroll
        for (int n = 0; n < 8; n++)
#pragma unroll
            for (int e = 0; e < 4; e++) s[n][e] = 0.f;

#pragma unroll
        for (int kk = 0; kk < 8; kk++) {
            const uint32_t ko = kk * 32;
            uint32_t q4[4];
            ldsm4(q4, pQ + ko);
            uint32_t kh[4][4], kl[4][4];
#pragma unroll
            for (int g4 = 0; g4 < 4; g4++) {
                ldsm4(kh[g4], pK + ko + g4 * (16 * SKS * 2));
                ldsm4(kl[g4], pK + KMATB + ko + g4 * (16 * SKS * 2));
            }
#pragma unroll
            for (int g4 = 0; g4 < 4; g4++) {
                mma16816h(s[g4 * 2],     q4, kh[g4][0], kh[g4][2]);
                mma16816h(s[g4 * 2 + 1], q4, kh[g4][1], kh[g4][3]);
            }
#pragma unroll
            for (int g4 = 0; g4 < 4; g4++) {
                mma16816h(s[g4 * 2],     q4, kl[g4][0], kl[g4][2]);
                mma16816h(s[g4 * 2 + 1], q4, kl[g4][1], kl[g4][3]);
            }
        }

        // ---- causal mask ----
        const int kbase = kt * 64;
        if (kt >= 2 * qt) {
            int rg0 = qbase + wq + (lane >> 2);
#pragma unroll
            for (int n = 0; n < 8; n++) {
                int cg = kbase + n * 8 + (lane & 3) * 2;
                if (cg > rg0)         s[n][0] = -1e30f;
                if (cg + 1 > rg0)     s[n][1] = -1e30f;
                if (cg > rg0 + 8)     s[n][2] = -1e30f;
                if (cg + 1 > rg0 + 8) s[n][3] = -1e30f;
            }
        }

        // ---- online softmax (exp2 domain) ----
        float mx0 = -1e30f, mx1 = -1e30f;
#pragma unroll
        for (int n = 0; n < 8; n++) {
            mx0 = fmaxf(mx0, fmaxf(s[n][0], s[n][1]));
            mx1 = fmaxf(mx1, fmaxf(s[n][2], s[n][3]));
        }
        mx0 = fmaxf(mx0, __shfl_xor_sync(0xffffffffu, mx0, 1));
        mx0 = fmaxf(mx0, __shfl_xor_sync(0xffffffffu, mx0, 2));
        mx1 = fmaxf(mx1, __shfl_xor_sync(0xffffffffu, mx1, 1));
        mx1 = fmaxf(mx1, __shfl_xor_sync(0xffffffffu, mx1, 2));
        float mn0 = fmaxf(m0, mx0), mn1 = fmaxf(m1, mx1);
        float c0 = ex2f(m0 - mn0), c1 = ex2f(m1 - mn1);
        float rs0 = 0.f, rs1 = 0.f;
#pragma unroll
        for (int n = 0; n < 8; n++) {
            s[n][0] = ex2f(s[n][0] - mn0); rs0 += s[n][0];
            s[n][1] = ex2f(s[n][1] - mn0); rs0 += s[n][1];
            s[n][2] = ex2f(s[n][2] - mn1); rs1 += s[n][2];
            s[n][3] = ex2f(s[n][3] - mn1); rs1 += s[n][3];
        }
        rs0 += __shfl_xor_sync(0xffffffffu, rs0, 1);
        rs0 += __shfl_xor_sync(0xffffffffu, rs0, 2);
        rs1 += __shfl_xor_sync(0xffffffffu, rs1, 1);
        rs1 += __shfl_xor_sync(0xffffffffu, rs1, 2);
        l0 = l0 * c0 + rs0; l1 = l1 * c1 + rs1;
        m0 = mn0; m1 = mn1;
#pragma unroll
        for (int d = 0; d < 16; d++) {
            o[d][0] *= c0; o[d][1] *= c0;
            o[d][2] *= c1; o[d][3] *= c1;
        }

        // ---- P (single fp16, A-layout) ----
        uint32_t aP[4][4];
#pragma unroll
        for (int kb = 0; kb < 4; kb++) {
            float* f0 = s[2 * kb];
            float* f1 = s[2 * kb + 1];
            aP[kb][0] = packh(f0[0], f0[1]);
            aP[kb][1] = packh(f0[2], f0[3]);
            aP[kb][2] = packh(f1[0], f1[1]);
            aP[kb][3] = packh(f1[2], f1[3]);
        }

        // ---- O += P @ (Vh + Vl) ----
#pragma unroll
        for (int kb = 0; kb < 4; kb++) {
            const uint32_t pvb = pV + kb * (16 * SKS * 2);
#pragma unroll
            for (int dp = 0; dp < 4; dp++) {
                uint32_t vh0[4], vh1[4], vl0[4], vl1[4];
                ldsm4t(vh0, pvb + (2 * dp) * 32);
                ldsm4t(vh1, pvb + (2 * dp + 1) * 32);
                ldsm4t(vl0, pvb + KMATB + (2 * dp) * 32);
                ldsm4t(vl1, pvb + KMATB + (2 * dp + 1) * 32);
                mma16816h(o[4 * dp],     aP[kb], vh0[0], vh0[1]);
                mma16816h(o[4 * dp + 1], aP[kb], vh0[2], vh0[3]);
                mma16816h(o[4 * dp + 2], aP[kb], vh1[0], vh1[1]);
                mma16816h(o[4 * dp + 3], aP[kb], vh1[2], vh1[3]);
                mma16816h(o[4 * dp],     aP[kb], vl0[0], vl0[1]);
                mma16816h(o[4 * dp + 1], aP[kb], vl0[2], vl0[3]);
                mma16816h(o[4 * dp + 2], aP[kb], vl1[0], vl1[1]);
                mma16816h(o[4 * dp + 3], aP[kb], vl1[2], vl1[3]);
            }
        }
        __syncthreads();
    }

    // ---- epilogue: O/l -> bf16 hi/lo ----
    float inv0 = 1.f / l0, inv1 = 1.f / l1;
    int row0 = qbase + wq + (lane >> 2);
    int colb = h * HD + (lane & 3) * 2;
#pragma unroll
    for (int dg = 0; dg < 16; dg++) {
        int col = colb + dg * 8;
        float v00 = o[dg][0] * inv0, v01 = o[dg][1] * inv0;
        float v10 = o[dg][2] * inv1, v11 = o[dg][3] * inv1;
        __nv_bfloat162 hA = __floats2bfloat162_rn(v00, v01);
        __nv_bfloat162 hB = __floats2bfloat162_rn(v10, v11);
        __nv_bfloat162 lA = __floats2bfloat162_rn(v00 - __bfloat162float(hA.x),
                                                  v01 - __bfloat162float(hA.y));
        __nv_bfloat162 lB = __floats2bfloat162_rn(v10 - __bfloat162float(hB.x),
                                                  v11 - __bfloat162float(hB.y));
        *(__nv_bfloat162*)(outh + (size_t)row0 * HID + col)       = hA;
        *(__nv_bfloat162*)(outl + (size_t)row0 * HID + col)       = lA;
        *(__nv_bfloat162*)(outh + (size_t)(row0 + 8) * HID + col) = hB;
        *(__nv_bfloat162*)(outl + (size_t)(row0 + 8) * HID + col) = lB;
    }
}

// ---------------------------------------------------------------------------
extern "C" void kernel_launch(void* const* d_in, const int* in_sizes, int n_in,
                              void* d_out, int out_size)
{
    const int*   positions = (const int*)d_in[0];
    const float* hidden    = (const float*)d_in[1];
    const float* w_qkv     = (const float*)d_in[2];
    const float* b_qkv     = (const float*)d_in[3];
    const float* w_o       = (const float*)d_in[4];
    float* out = (float*)d_out;

    float *qkv, *ct, *st;
    __nv_bfloat16 *hidh, *hidl, *wqh, *wql, *woh, *wol, *ath, *atl;
    __half *qkvh, *qkvl;
    cudaGetSymbolAddress((void**)&qkv,  g_qkv);
    cudaGetSymbolAddress((void**)&ct,   g_cos);
    cudaGetSymbolAddress((void**)&st,   g_sin);
    cudaGetSymbolAddress((void**)&hidh, g_hidh);
    cudaGetSymbolAddress((void**)&hidl, g_hidl);
    cudaGetSymbolAddress((void**)&wqh,  g_wqh);
    cudaGetSymbolAddress((void**)&wql,  g_wql);
    cudaGetSymbolAddress((void**)&woh,  g_woh);
    cudaGetSymbolAddress((void**)&wol,  g_wol);
    cudaGetSymbolAddress((void**)&qkvh, g_qkvh);
    cudaGetSymbolAddress((void**)&qkvl, g_qkvl);
    cudaGetSymbolAddress((void**)&ath,  g_attnh);
    cudaGetSymbolAddress((void**)&atl,  g_attnl);

    cudaFuncSetAttribute(gemm_bf,
                         cudaFuncAttributeMaxDynamicSharedMemorySize, GB_SMEM);
    cudaFuncSetAttribute(attn_mma,
                         cudaFuncAttributeMaxDynamicSharedMemorySize, AT_SMEM);

    // 0) split GEMM inputs to bf16 hi/lo
    {
        int n1 = T_SEQ * HID;
        split_plain<<<n1 / 1024, 256>>>(hidden, hidh, hidl, n1);
        int n2 = QKV_N * HID;
        split_plain<<<n2 / 1024, 256>>>(w_qkv, wqh, wql, n2);
        int n3 = HID * HID;
        split_plain<<<n3 / 1024, 256>>>(w_o, woh, wol, n3);
    }

    // 1) qkv = hidden @ w_qkv^T + b_qkv (fp32 out)
    dim3 g1(QKV_N / 128, T_SEQ / 128);
    gemm_bf<<<g1, 256, GB_SMEM>>>(hidh, hidl, wqh, wql, b_qkv, qkv,
                                  T_SEQ, QKV_N, HID);

    // 2) RoPE + fp16 hi/lo split (fused); v split separately
    int nt = T_SEQ * (HD / 2);
    rope_table_kernel<<<(nt + 255) / 256, 256>>>(positions, ct, st);
    int nr = T_SEQ * (NH + NKV) * 16;
    rope_split_kernel<<<nr / 256, 256>>>(qkv, ct, st, qkvh, qkvl);
    int nv = T_SEQ * 64;
    split_v_kernel<<<nv / 256, 256>>>(qkv, qkvh, qkvl);

    // 3) flash attention (fp16 HMMA), writes bf16 hi/lo attn output
    attn_mma<<<dim3(T_SEQ / 128, NH), 256, AT_SMEM>>>(qkvh, qkvl, ath, atl);

    // 4) out = attn @ w_o^T
    dim3 g2(HID / 128, T_SEQ / 128);
    gemm_bf<<<g2, 256, GB_SMEM>>>(ath, atl, woh, wol, nullptr, out,
                                  T_SEQ, HID, HID);
}

// round 6
// speedup vs baseline: 6.0553x; 1.1884x over previous
#include <cuda_runtime.h>
#include <cuda_fp16.h>
#include <math.h>
#include <stdint.h>

#define T_SEQ 4096
#define HID   2048
#define NH    16
#define NKV   2
#define HD    128
#define QKV_N ((NH + 2*NKV)*HD)   // 2560
#define GQA   (NH/NKV)            // 8

// ---------------------------------------------------------------------------
// Device-global scratch
// ---------------------------------------------------------------------------
__device__ float g_qkv[4096 * 2560];                  // fp32 qkv (pre-RoPE)
__device__ __half g_hidh[4096 * 2048], g_hidl[4096 * 2048];
__device__ __half g_wq[2560 * 2048];
__device__ __half g_wo[2048 * 2048];
__device__ __half g_qkvh[4096 * 2560], g_qkvl[4096 * 2560];
__device__ __half g_attnh[4096 * 2048], g_attnl[4096 * 2048];
__device__ float g_cos[4096 * 64];
__device__ float g_sin[4096 * 64];

// ---------------------------------------------------------------------------
// Helpers
// ---------------------------------------------------------------------------
__device__ __forceinline__ uint32_t su32(const void* p) {
    uint32_t a;
    asm("{ .reg .u64 t; cvta.to.shared.u64 t, %1; cvt.u32.u64 %0, t; }"
        : "=r"(a) : "l"(p));
    return a;
}
__device__ __forceinline__ void ldsm4(uint32_t* r, uint32_t addr) {
    asm volatile("ldmatrix.sync.aligned.m8n8.x4.shared.b16 {%0,%1,%2,%3}, [%4];"
                 : "=r"(r[0]), "=r"(r[1]), "=r"(r[2]), "=r"(r[3]) : "r"(addr));
}
__device__ __forceinline__ void ldsm4t(uint32_t* r, uint32_t addr) {
    asm volatile("ldmatrix.sync.aligned.m8n8.x4.trans.shared.b16 {%0,%1,%2,%3}, [%4];"
                 : "=r"(r[0]), "=r"(r[1]), "=r"(r[2]), "=r"(r[3]) : "r"(addr));
}
__device__ __forceinline__ void mma16816h(float* c, const uint32_t* a,
                                          uint32_t b0, uint32_t b1) {
    asm volatile(
        "mma.sync.aligned.m16n8k16.row.col.f32.f16.f16.f32 "
        "{%0,%1,%2,%3}, {%4,%5,%6,%7}, {%8,%9}, {%0,%1,%2,%3};"
        : "+f"(c[0]), "+f"(c[1]), "+f"(c[2]), "+f"(c[3])
        : "r"(a[0]), "r"(a[1]), "r"(a[2]), "r"(a[3]), "r"(b0), "r"(b1));
}
__device__ __forceinline__ void cp_async8(uint32_t smem, const void* g) {
    asm volatile("cp.async.ca.shared.global [%0], [%1], 8;" :: "r"(smem), "l"(g));
}
__device__ __forceinline__ void cp_async16(uint32_t smem, const void* g) {
    asm volatile("cp.async.cg.shared.global [%0], [%1], 16;" :: "r"(smem), "l"(g));
}
#define CP_COMMIT() asm volatile("cp.async.commit_group;" ::: "memory")
#define CP_WAIT0()  asm volatile("cp.async.wait_group 0;" ::: "memory")
#define CP_WAIT1()  asm volatile("cp.async.wait_group 1;" ::: "memory")

__device__ __forceinline__ float ex2f(float x) {
    float y;
    asm("ex2.approx.ftz.f32 %0, %1;" : "=f"(y) : "f"(x));
    return y;
}
__device__ __forceinline__ uint32_t packh(float x, float y) {
    __half2 t = __floats2half2_rn(x, y);
    return *(uint32_t*)&t;
}

// ---------------------------------------------------------------------------
// Split / convert kernels (fp32 -> fp16 hi/lo, fp32 -> fp16)
// ---------------------------------------------------------------------------
__device__ __forceinline__ void split4h(float4 v, __half* hi, __half* lo) {
    __half h0 = __float2half_rn(v.x), h1 = __float2half_rn(v.y);
    __half h2 = __float2half_rn(v.z), h3 = __float2half_rn(v.w);
    uint64_t wh = (uint64_t)__half_as_ushort(h0)
                | ((uint64_t)__half_as_ushort(h1) << 16)
                | ((uint64_t)__half_as_ushort(h2) << 32)
                | ((uint64_t)__half_as_ushort(h3) << 48);
    __half l0 = __float2half_rn(v.x - __half2float(h0));
    __half l1 = __float2half_rn(v.y - __half2float(h1));
    __half l2 = __float2half_rn(v.z - __half2float(h2));
    __half l3 = __float2half_rn(v.w - __half2float(h3));
    uint64_t wl = (uint64_t)__half_as_ushort(l0)
                | ((uint64_t)__half_as_ushort(l1) << 16)
                | ((uint64_t)__half_as_ushort(l2) << 32)
                | ((uint64_t)__half_as_ushort(l3) << 48);
    *(uint64_t*)hi = wh;
    *(uint64_t*)lo = wl;
}

__global__ void split_h(const float* __restrict__ in,
                        __half* __restrict__ hi, __half* __restrict__ lo, int n)
{
    int i = (blockIdx.x * blockDim.x + threadIdx.x) * 4;
    if (i >= n) return;
    split4h(*(const float4*)(in + i), hi + i, lo + i);
}

__global__ void conv_h(const float* __restrict__ in, __half* __restrict__ out, int n)
{
    int i = (blockIdx.x * blockDim.x + threadIdx.x) * 4;
    if (i >= n) return;
    float4 v = *(const float4*)(in + i);
    __half2 a = __floats2half2_rn(v.x, v.y);
    __half2 b = __floats2half2_rn(v.z, v.w);
    *(uint2*)(out + i) = make_uint2(*(uint32_t*)&a, *(uint32_t*)&b);
}

// ---------------------------------------------------------------------------
// RoPE table + fused rope+fp16 split for q/k; fp16 split for v
// ---------------------------------------------------------------------------
__global__ void rope_table_kernel(const int* __restrict__ pos,
                                  float* __restrict__ ct, float* __restrict__ st)
{
    int idx = blockIdx.x * blockDim.x + threadIdx.x;
    if (idx >= T_SEQ * (HD / 2)) return;
    int d = idx & 63;
    int t = idx >> 6;
    double inv = exp(-((double)(2 * d) / (double)HD) * 9.210340371976184);
    double ang = (double)pos[t] * inv;
    ct[idx] = (float)cos(ang);
    st[idx] = (float)sin(ang);
}

#define QSC (0.08838834764831845f * 1.4426950408889634f)  // 1/sqrt(HD) * log2(e)

__global__ void rope_split_kernel(const float* __restrict__ qkv,
                                  const float* __restrict__ ct,
                                  const float* __restrict__ st,
                                  __half* __restrict__ oh, __half* __restrict__ ol)
{
    int idx = blockIdx.x * blockDim.x + threadIdx.x;
    if (idx >= T_SEQ * (NH + NKV) * 16) return;
    int c16 = idx & 15;
    int h = (idx >> 4) % (NH + NKV);
    int t = idx / ((NH + NKV) * 16);
    int d = c16 * 4;
    const float* base = qkv + (size_t)t * QKV_N + h * HD;
    float4 x1 = *(const float4*)(base + d);
    float4 x2 = *(const float4*)(base + d + 64);
    float4 c = *(const float4*)(ct + t * 64 + d);
    float4 s = *(const float4*)(st + t * 64 + d);
    float4 y1, y2;
    y1.x = x1.x * c.x - x2.x * s.x;  y2.x = x2.x * c.x + x1.x * s.x;
    y1.y = x1.y * c.y - x2.y * s.y;  y2.y = x2.y * c.y + x1.y * s.y;
    y1.z = x1.z * c.z - x2.z * s.z;  y2.z = x2.z * c.z + x1.z * s.z;
    y1.w = x1.w * c.w - x2.w * s.w;  y2.w = x2.w * c.w + x1.w * s.w;
    if (h < NH) {
        y1.x *= QSC; y1.y *= QSC; y1.z *= QSC; y1.w *= QSC;
        y2.x *= QSC; y2.y *= QSC; y2.z *= QSC; y2.w *= QSC;
    }
    size_t o = (size_t)t * QKV_N + h * HD + d;
    split4h(y1, oh + o,      ol + o);
    split4h(y2, oh + o + 64, ol + o + 64);
}

__global__ void split_v_kernel(const float* __restrict__ qkv,
                               __half* __restrict__ oh, __half* __restrict__ ol)
{
    int idx = blockIdx.x * blockDim.x + threadIdx.x;
    if (idx >= T_SEQ * 64) return;
    int t = idx >> 6;
    int c = (idx & 63) * 4 + (NH + NKV) * HD;
    size_t o = (size_t)t * QKV_N + c;
    split4h(*(const float4*)(qkv + o), oh + o, ol + o);
}

// ===========================================================================
// 2-term fp16 GEMM: C[M,N] = (Ah+Al)[M,K] @ B[N,K]^T (+bias).
// Error = A @ Blo dropped ~= 2^-11 statistical. 128x128 tile, BK=32, 8 warps,
// cp.async 2-stage. Per BK stage: 64 MMAs, 16 ldsm4.
// ===========================================================================
#define GS 40
#define MATB (128 * GS * 2)                 // bytes per matrix per stage
#define G2_STAGE (3 * 128 * GS)             // halves per stage (Ah, Al, Bh)
#define G2_SMEM  (2 * G2_STAGE * 2)         // 61440 bytes

__global__ void __launch_bounds__(256, 2)
gemm_2t(const __half* __restrict__ Ah_g, const __half* __restrict__ Al_g,
        const __half* __restrict__ B_g,
        const float* __restrict__ bias, float* __restrict__ C,
        int M, int N, int K)
{
    extern __shared__ __half smg[];
    const int tid = threadIdx.x, wid = tid >> 5, lane = tid & 31;
    const int bm = blockIdx.y * 128, bn = blockIdx.x * 128;
    const int wm = (wid & 3) * 32, wn = (wid >> 2) * 64;

    float acc[2][8][4];
#pragma unroll
    for (int i = 0; i < 2; i++)
#pragma unroll
        for (int n = 0; n < 8; n++)
#pragma unroll
            for (int e = 0; e < 4; e++) acc[i][n][e] = 0.f;

    const int S = K / 32;

    auto issue = [&](int buf, int s) {
        __half* base = smg + buf * G2_STAGE;
        const int k0 = s * 32;
#pragma unroll
        for (int i = 0; i < 12; i++) {
            int c = tid + i * 256;          // 3072 chunks of 8B
            int mat = c >> 10;              // 0 Ah, 1 Al, 2 Bh
            int w = c & 1023;
            int row = w >> 3, cc = w & 7;
            const __half* src =
                (mat == 0) ? Ah_g + (size_t)(bm + row) * K + k0 + cc * 4 :
                (mat == 1) ? Al_g + (size_t)(bm + row) * K + k0 + cc * 4 :
                             B_g  + (size_t)(bn + row) * K + k0 + cc * 4;
            cp_async8(su32(base + mat * (128 * GS) + row * GS + cc * 4), src);
        }
    };

    issue(0, 0); CP_COMMIT();

    const int a_r = lane & 15, a_k = (lane >> 4) * 8;
    const int b_n = ((lane >> 3) & 1) * 8 + (lane & 7), b_k = (lane >> 4) * 8;
    const uint32_t smb = su32(smg);
    const uint32_t a_base = 2 * ((wm + a_r) * GS + a_k);
    const uint32_t b_base = 2 * ((wn + b_n) * GS + b_k);

    for (int s = 0; s < S; s++) {
        if (s + 1 < S) { issue((s + 1) & 1, s + 1); CP_COMMIT(); CP_WAIT1(); }
        else CP_WAIT0();
        __syncthreads();

        const uint32_t stb = smb + (s & 1) * (G2_STAGE * 2);
        const uint32_t pAh = stb + a_base;
        const uint32_t pAl = pAh + MATB;
        const uint32_t pB  = stb + 2 * MATB + b_base;

#pragma unroll
        for (int kk = 0; kk < 2; kk++) {
            const uint32_t ko = kk * 32;
            uint32_t ah[2][4], al[2][4];
            ldsm4(ah[0], pAh + ko);
            ldsm4(ah[1], pAh + ko + 16 * GS * 2);
            ldsm4(al[0], pAl + ko);
            ldsm4(al[1], pAl + ko + 16 * GS * 2);
#pragma unroll
            for (int np = 0; np < 4; np++) {
                uint32_t bh[4];
                ldsm4(bh, pB + ko + np * (16 * GS * 2));
                mma16816h(acc[0][np * 2],     ah[0], bh[0], bh[2]);
                mma16816h(acc[0][np * 2 + 1], ah[0], bh[1], bh[3]);
                mma16816h(acc[1][np * 2],     ah[1], bh[0], bh[2]);
                mma16816h(acc[1][np * 2 + 1], ah[1], bh[1], bh[3]);
                mma16816h(acc[0][np * 2],     al[0], bh[0], bh[2]);
                mma16816h(acc[0][np * 2 + 1], al[0], bh[1], bh[3]);
                mma16816h(acc[1][np * 2],     al[1], bh[0], bh[2]);
                mma16816h(acc[1][np * 2 + 1], al[1], bh[1], bh[3]);
            }
        }
        __syncthreads();
    }

    const int tr = lane >> 2;
    const int tc = (lane & 3) * 2;
#pragma unroll
    for (int i = 0; i < 2; i++) {
#pragma unroll
        for (int n = 0; n < 8; n++) {
            int col = bn + wn + n * 8 + tc;
            float bb0 = bias ? bias[col]     : 0.f;
            float bb1 = bias ? bias[col + 1] : 0.f;
            int row0 = bm + wm + i * 16 + tr;
            float2 v0 = make_float2(acc[i][n][0] + bb0, acc[i][n][1] + bb1);
            float2 v1 = make_float2(acc[i][n][2] + bb0, acc[i][n][3] + bb1);
            *(float2*)&C[(size_t)row0 * N + col]       = v0;
            *(float2*)&C[(size_t)(row0 + 8) * N + col] = v1;
        }
    }
}

// ===========================================================================
// fp16 HMMA flash attention. Q single fp16 held in REGISTERS across all
// k-tiles; K hi/lo, V hi/lo, P single fp16.
// Q-tile 128 x K-tile 64, 8 warps, cp.async double-buffered KV.
// Output written as fp16 hi/lo (feeds o-proj A operand).
// ===========================================================================
#define SKS 136
#define AT_QSZ (128 * SKS)                  // halves
#define AT_KSZ (64 * SKS)                   // halves per matrix
#define KMATB  (AT_KSZ * 2)                 // bytes per matrix
#define AT_STAGEB (4 * KMATB)               // bytes per KV stage
#define AT_SMEM (AT_QSZ * 2 + 2 * AT_STAGEB)  // 174080 bytes

__global__ void __launch_bounds__(256, 1)
attn_mma(const __half* __restrict__ qkvh,
         const __half* __restrict__ qkvl,
         __half* __restrict__ outh,
         __half* __restrict__ outl)
{
    extern __shared__ __half sma[];
    __half* Qs = sma;
    __half* KV = sma + AT_QSZ;

    const int tid = threadIdx.x, wid = tid >> 5, lane = tid & 31;
    const int h = blockIdx.y;
    const int qt = (int)gridDim.x - 1 - (int)blockIdx.x;   // heavy tiles first
    const int qbase = qt * 128;
    const int g = h >> 3;
    const int qoff = h * HD;
    const int koff = NH * HD + g * HD;
    const int voff = (NH + NKV) * HD + g * HD;

    // ---- load Q tile to smem, then hoist fragments into registers ----
#pragma unroll
    for (int i = 0; i < 8; i++) {
        int c = tid + i * 256;
        int row = c >> 4, cc = c & 15;
        const __half* src = qkvh + (size_t)(qbase + row) * QKV_N + qoff + cc * 8;
        *(uint4*)(Qs + row * SKS + cc * 8) = *(const uint4*)src;
    }

    auto load_kv = [&](int buf, int kt) {
        const int kbase = kt * 64;
        __half* base = KV + buf * (4 * AT_KSZ);
#pragma unroll
        for (int i = 0; i < 16; i++) {
            int c = tid + i * 256;
            int mat = c >> 10;            // 0 Kh, 1 Kl, 2 Vh, 3 Vl
            int w = c & 1023;
            int row = w >> 4, cc = w & 15;
            const __half* src = ((mat & 1) ? qkvl : qkvh)
                + (size_t)(kbase + row) * QKV_N + ((mat >> 1) ? voff : koff) + cc * 8;
            cp_async16(su32(base + mat * AT_KSZ + row * SKS + cc * 8), src);
        }
    };

    const int nkt = 2 * qt + 2;
    load_kv(0, 0); CP_COMMIT();

    const int wq = wid * 16;
    const int a_r = lane & 15, a_k = (lane >> 4) * 8;
    const int b_n = ((lane >> 3) & 1) * 8 + (lane & 7), b_k = (lane >> 4) * 8;

    const uint32_t smb = su32(sma);
    const uint32_t pQ = smb + 2 * ((wq + a_r) * SKS + a_k);
    const uint32_t bk_base = 2 * (b_n * SKS + b_k);

    __syncthreads();   // Q stores visible
    uint32_t qf[8][4];
#pragma unroll
    for (int kk = 0; kk < 8; kk++) ldsm4(qf[kk], pQ + kk * 32);

    float o[16][4];
#pragma unroll
    for (int d = 0; d < 16; d++)
#pragma unroll
        for (int e = 0; e < 4; e++) o[d][e] = 0.f;
    float m0 = -1e30f, m1 = -1e30f, l0 = 0.f, l1 = 0.f;

    for (int kt = 0; kt < nkt; kt++) {
        if (kt + 1 < nkt) { load_kv((kt + 1) & 1, kt + 1); CP_COMMIT(); CP_WAIT1(); }
        else CP_WAIT0();
        __syncthreads();

        const uint32_t kvb = smb + AT_QSZ * 2 + (kt & 1) * AT_STAGEB;
        const uint32_t pK = kvb + bk_base;
        const uint32_t pV = kvb + 2 * KMATB + bk_base;

        // ---- S = Qh @ (Kh + Kl)^T ----
        float s[8][4];
#pragma unroll
        for (int n = 0; n < 8; n++)
#pragma unroll
            for (int e = 0; e < 4; e++) s[n][e] = 0.f;

#pragma unroll
        for (int kk = 0; kk < 8; kk++) {
            const uint32_t ko = kk * 32;
            uint32_t kh[4][4], kl[4][4];
#pragma unroll
            for (int g4 = 0; g4 < 4; g4++) {
                ldsm4(kh[g4], pK + ko + g4 * (16 * SKS * 2));
                ldsm4(kl[g4], pK + KMATB + ko + g4 * (16 * SKS * 2));
            }
#pragma unroll
            for (int g4 = 0; g4 < 4; g4++) {
                mma16816h(s[g4 * 2],     qf[kk], kh[g4][0], kh[g4][2]);
                mma16816h(s[g4 * 2 + 1], qf[kk], kh[g4][1], kh[g4][3]);
            }
#pragma unroll
            for (int g4 = 0; g4 < 4; g4++) {
                mma16816h(s[g4 * 2],     qf[kk], kl[g4][0], kl[g4][2]);
                mma16816h(s[g4 * 2 + 1], qf[kk], kl[g4][1], kl[g4][3]);
            }
        }

        // ---- causal mask ----
        const int kbase = kt * 64;
        if (kt >= 2 * qt) {
            int rg0 = qbase + wq + (lane >> 2);
#pragma unroll
            for (int n = 0; n < 8; n++) {
                int cg = kbase + n * 8 + (lane & 3) * 2;
                if (cg > rg0)         s[n][0] = -1e30f;
                if (cg + 1 > rg0)     s[n][1] = -1e30f;
                if (cg > rg0 + 8)     s[n][2] = -1e30f;
                if (cg + 1 > rg0 + 8) s[n][3] = -1e30f;
            }
        }

        // ---- online softmax (exp2 domain) ----
        float mx0 = -1e30f, mx1 = -1e30f;
#pragma unroll
        for (int n = 0; n < 8; n++) {
            mx0 = fmaxf(mx0, fmaxf(s[n][0], s[n][1]));
            mx1 = fmaxf(mx1, fmaxf(s[n][2], s[n][3]));
        }
        mx0 = fmaxf(mx0, __shfl_xor_sync(0xffffffffu, mx0, 1));
        mx0 = fmaxf(mx0, __shfl_xor_sync(0xffffffffu, mx0, 2));
        mx1 = fmaxf(mx1, __shfl_xor_sync(0xffffffffu, mx1, 1));
        mx1 = fmaxf(mx1, __shfl_xor_sync(0xffffffffu, mx1, 2));
        float mn0 = fmaxf(m0, mx0), mn1 = fmaxf(m1, mx1);
        float c0 = ex2f(m0 - mn0), c1 = ex2f(m1 - mn1);
        float rs0 = 0.f, rs1 = 0.f;
#pragma unroll
        for (int n = 0; n < 8; n++) {
            s[n][0] = ex2f(s[n][0] - mn0); rs0 += s[n][0];
            s[n][1] = ex2f(s[n][1] - mn0); rs0 += s[n][1];
            s[n][2] = ex2f(s[n][2] - mn1); rs1 += s[n][2];
            s[n][3] = ex2f(s[n][3] - mn1); rs1 += s[n][3];
        }
        rs0 += __shfl_xor_sync(0xffffffffu, rs0, 1);
        rs0 += __shfl_xor_sync(0xffffffffu, rs0, 2);
        rs1 += __shfl_xor_sync(0xffffffffu, rs1, 1);
        rs1 += __shfl_xor_sync(0xffffffffu, rs1, 2);
        l0 = l0 * c0 + rs0; l1 = l1 * c1 + rs1;
        m0 = mn0; m1 = mn1;
#pragma unroll
        for (int d = 0; d < 16; d++) {
            o[d][0] *= c0; o[d][1] *= c0;
            o[d][2] *= c1; o[d][3] *= c1;
        }

        // ---- P (single fp16, A-layout) ----
        uint32_t aP[4][4];
#pragma unroll
        for (int kb = 0; kb < 4; kb++) {
            float* f0 = s[2 * kb];
            float* f1 = s[2 * kb + 1];
            aP[kb][0] = packh(f0[0], f0[1]);
            aP[kb][1] = packh(f0[2], f0[3]);
            aP[kb][2] = packh(f1[0], f1[1]);
            aP[kb][3] = packh(f1[2], f1[3]);
        }

        // ---- O += P @ (Vh + Vl) ----
#pragma unroll
        for (int kb = 0; kb < 4; kb++) {
            const uint32_t pvb = pV + kb * (16 * SKS * 2);
#pragma unroll
            for (int dp = 0; dp < 4; dp++) {
                uint32_t vh0[4], vh1[4], vl0[4], vl1[4];
                ldsm4t(vh0, pvb + (2 * dp) * 32);
                ldsm4t(vh1, pvb + (2 * dp + 1) * 32);
                ldsm4t(vl0, pvb + KMATB + (2 * dp) * 32);
                ldsm4t(vl1, pvb + KMATB + (2 * dp + 1) * 32);
                mma16816h(o[4 * dp],     aP[kb], vh0[0], vh0[1]);
                mma16816h(o[4 * dp + 1], aP[kb], vh0[2], vh0[3]);
                mma16816h(o[4 * dp + 2], aP[kb], vh1[0], vh1[1]);
                mma16816h(o[4 * dp + 3], aP[kb], vh1[2], vh1[3]);
                mma16816h(o[4 * dp],     aP[kb], vl0[0], vl0[1]);
                mma16816h(o[4 * dp + 1], aP[kb], vl0[2], vl0[3]);
                mma16816h(o[4 * dp + 2], aP[kb], vl1[0], vl1[1]);
                mma16816h(o[4 * dp + 3], aP[kb], vl1[2], vl1[3]);
            }
        }
        __syncthreads();
    }

    // ---- epilogue: O/l -> fp16 hi/lo ----
    float inv0 = 1.f / l0, inv1 = 1.f / l1;
    int row0 = qbase + wq + (lane >> 2);
    int colb = h * HD + (lane & 3) * 2;
#pragma unroll
    for (int dg = 0; dg < 16; dg++) {
        int col = colb + dg * 8;
        float v00 = o[dg][0] * inv0, v01 = o[dg][1] * inv0;
        float v10 = o[dg][2] * inv1, v11 = o[dg][3] * inv1;
        __half2 hA = __floats2half2_rn(v00, v01);
        __half2 hB = __floats2half2_rn(v10, v11);
        __half2 lA = __floats2half2_rn(v00 - __half2float(hA.x),
                                       v01 - __half2float(hA.y));
        __half2 lB = __floats2half2_rn(v10 - __half2float(hB.x),
                                       v11 - __half2float(hB.y));
        *(__half2*)(outh + (size_t)row0 * HID + col)       = hA;
        *(__half2*)(outl + (size_t)row0 * HID + col)       = lA;
        *(__half2*)(outh + (size_t)(row0 + 8) * HID + col) = hB;
        *(__half2*)(outl + (size_t)(row0 + 8) * HID + col) = lB;
    }
}

// ---------------------------------------------------------------------------
extern "C" void kernel_launch(void* const* d_in, const int* in_sizes, int n_in,
                              void* d_out, int out_size)
{
    const int*   positions = (const int*)d_in[0];
    const float* hidden    = (const float*)d_in[1];
    const float* w_qkv     = (const float*)d_in[2];
    const float* b_qkv     = (const float*)d_in[3];
    const float* w_o       = (const float*)d_in[4];
    float* out = (float*)d_out;

    float *qkv, *ct, *st;
    __half *hidh, *hidl, *wq, *wo, *qkvh, *qkvl, *ath, *atl;
    cudaGetSymbolAddress((void**)&qkv,  g_qkv);
    cudaGetSymbolAddress((void**)&ct,   g_cos);
    cudaGetSymbolAddress((void**)&st,   g_sin);
    cudaGetSymbolAddress((void**)&hidh, g_hidh);
    cudaGetSymbolAddress((void**)&hidl, g_hidl);
    cudaGetSymbolAddress((void**)&wq,   g_wq);
    cudaGetSymbolAddress((void**)&wo,   g_wo);
    cudaGetSymbolAddress((void**)&qkvh, g_qkvh);
    cudaGetSymbolAddress((void**)&qkvl, g_qkvl);
    cudaGetSymbolAddress((void**)&ath,  g_attnh);
    cudaGetSymbolAddress((void**)&atl,  g_attnl);

    cudaFuncSetAttribute(gemm_2t,
                         cudaFuncAttributeMaxDynamicSharedMemorySize, G2_SMEM);
    cudaFuncSetAttribute(attn_mma,
                         cudaFuncAttributeMaxDynamicSharedMemorySize, AT_SMEM);

    // 0) prep inputs
    {
        int n1 = T_SEQ * HID;
        split_h<<<n1 / 1024, 256>>>(hidden, hidh, hidl, n1);
        int n2 = QKV_N * HID;
        conv_h<<<n2 / 1024, 256>>>(w_qkv, wq, n2);
        int n3 = HID * HID;
        conv_h<<<n3 / 1024, 256>>>(w_o, wo, n3);
    }

    // 1) qkv = hidden @ w_qkv^T + b_qkv (fp32 out)
    dim3 g1(QKV_N / 128, T_SEQ / 128);
    gemm_2t<<<g1, 256, G2_SMEM>>>(hidh, hidl, wq, b_qkv, qkv,
                                  T_SEQ, QKV_N, HID);

    // 2) RoPE + fp16 hi/lo split
    int nt = T_SEQ * (HD / 2);
    rope_table_kernel<<<(nt + 255) / 256, 256>>>(positions, ct, st);
    int nr = T_SEQ * (NH + NKV) * 16;
    rope_split_kernel<<<nr / 256, 256>>>(qkv, ct, st, qkvh, qkvl);
    int nv = T_SEQ * 64;
    split_v_kernel<<<nv / 256, 256>>>(qkv, qkvh, qkvl);

    // 3) flash attention (fp16 HMMA), writes fp16 hi/lo attn output
    attn_mma<<<dim3(T_SEQ / 128, NH), 256, AT_SMEM>>>(qkvh, qkvl, ath, atl);

    // 4) out = attn @ w_o^T
    dim3 g2(HID / 128, T_SEQ / 128);
    gemm_2t<<<g2, 256, G2_SMEM>>>(ath, atl, wo, nullptr, out,
                                  T_SEQ, HID, HID);
}

// round 7
// speedup vs baseline: 7.3332x; 1.2110x over previous
#include <cuda_runtime.h>
#include <cuda_fp16.h>
#include <math.h>
#include <stdint.h>

#define T_SEQ 4096
#define HID   2048
#define NH    16
#define NKV   2
#define HD    128
#define QKV_N ((NH + 2*NKV)*HD)   // 2560
#define GQA   (NH/NKV)            // 8

// ---------------------------------------------------------------------------
// Device-global scratch
// ---------------------------------------------------------------------------
__device__ float g_qkv[4096 * 2560];                  // fp32 qkv (pre-RoPE)
__device__ __half g_hidh[4096 * 2048], g_hidl[4096 * 2048];
__device__ __half g_wq[2560 * 2048];
__device__ __half g_wo[2048 * 2048];
__device__ __half g_qkvh[4096 * 2560], g_qkvl[4096 * 2560];
__device__ __half g_attn[4096 * 2048];
__device__ float g_cos[4096 * 64];
__device__ float g_sin[4096 * 64];

// ---------------------------------------------------------------------------
// Helpers
// ---------------------------------------------------------------------------
__device__ __forceinline__ uint32_t su32(const void* p) {
    uint32_t a;
    asm("{ .reg .u64 t; cvta.to.shared.u64 t, %1; cvt.u32.u64 %0, t; }"
        : "=r"(a) : "l"(p));
    return a;
}
__device__ __forceinline__ void ldsm4(uint32_t* r, uint32_t addr) {
    asm volatile("ldmatrix.sync.aligned.m8n8.x4.shared.b16 {%0,%1,%2,%3}, [%4];"
                 : "=r"(r[0]), "=r"(r[1]), "=r"(r[2]), "=r"(r[3]) : "r"(addr));
}
__device__ __forceinline__ void ldsm4t(uint32_t* r, uint32_t addr) {
    asm volatile("ldmatrix.sync.aligned.m8n8.x4.trans.shared.b16 {%0,%1,%2,%3}, [%4];"
                 : "=r"(r[0]), "=r"(r[1]), "=r"(r[2]), "=r"(r[3]) : "r"(addr));
}
__device__ __forceinline__ void mma16816h(float* c, const uint32_t* a,
                                          uint32_t b0, uint32_t b1) {
    asm volatile(
        "mma.sync.aligned.m16n8k16.row.col.f32.f16.f16.f32 "
        "{%0,%1,%2,%3}, {%4,%5,%6,%7}, {%8,%9}, {%0,%1,%2,%3};"
        : "+f"(c[0]), "+f"(c[1]), "+f"(c[2]), "+f"(c[3])
        : "r"(a[0]), "r"(a[1]), "r"(a[2]), "r"(a[3]), "r"(b0), "r"(b1));
}
__device__ __forceinline__ void cp_async8(uint32_t smem, const void* g) {
    asm volatile("cp.async.ca.shared.global [%0], [%1], 8;" :: "r"(smem), "l"(g));
}
__device__ __forceinline__ void cp_async16(uint32_t smem, const void* g) {
    asm volatile("cp.async.cg.shared.global [%0], [%1], 16;" :: "r"(smem), "l"(g));
}
#define CP_COMMIT() asm volatile("cp.async.commit_group;" ::: "memory")
#define CP_WAIT0()  asm volatile("cp.async.wait_group 0;" ::: "memory")
#define CP_WAIT1()  asm volatile("cp.async.wait_group 1;" ::: "memory")
#define CP_WAIT2()  asm volatile("cp.async.wait_group 2;" ::: "memory")
// Wait so that stage s is complete when stages up to lim = min(S-1, s+2) issued.
#define STAGE_WAIT(s, S) do { \
    if ((s) + 2 < (S)) { CP_WAIT2(); } \
    else if ((s) + 1 < (S)) { CP_WAIT1(); } \
    else { CP_WAIT0(); } \
} while (0)

__device__ __forceinline__ float ex2f(float x) {
    float y;
    asm("ex2.approx.ftz.f32 %0, %1;" : "=f"(y) : "f"(x));
    return y;
}
__device__ __forceinline__ uint32_t packh(float x, float y) {
    __half2 t = __floats2half2_rn(x, y);
    return *(uint32_t*)&t;
}

// ---------------------------------------------------------------------------
// Split / convert kernels
// ---------------------------------------------------------------------------
__device__ __forceinline__ void split4h(float4 v, __half* hi, __half* lo) {
    __half h0 = __float2half_rn(v.x), h1 = __float2half_rn(v.y);
    __half h2 = __float2half_rn(v.z), h3 = __float2half_rn(v.w);
    uint64_t wh = (uint64_t)__half_as_ushort(h0)
                | ((uint64_t)__half_as_ushort(h1) << 16)
                | ((uint64_t)__half_as_ushort(h2) << 32)
                | ((uint64_t)__half_as_ushort(h3) << 48);
    __half l0 = __float2half_rn(v.x - __half2float(h0));
    __half l1 = __float2half_rn(v.y - __half2float(h1));
    __half l2 = __float2half_rn(v.z - __half2float(h2));
    __half l3 = __float2half_rn(v.w - __half2float(h3));
    uint64_t wl = (uint64_t)__half_as_ushort(l0)
                | ((uint64_t)__half_as_ushort(l1) << 16)
                | ((uint64_t)__half_as_ushort(l2) << 32)
                | ((uint64_t)__half_as_ushort(l3) << 48);
    *(uint64_t*)hi = wh;
    *(uint64_t*)lo = wl;
}

__global__ void split_h(const float* __restrict__ in,
                        __half* __restrict__ hi, __half* __restrict__ lo, int n)
{
    int i = (blockIdx.x * blockDim.x + threadIdx.x) * 4;
    if (i >= n) return;
    split4h(*(const float4*)(in + i), hi + i, lo + i);
}

__global__ void conv_h(const float* __restrict__ in, __half* __restrict__ out, int n)
{
    int i = (blockIdx.x * blockDim.x + threadIdx.x) * 4;
    if (i >= n) return;
    float4 v = *(const float4*)(in + i);
    __half2 a = __floats2half2_rn(v.x, v.y);
    __half2 b = __floats2half2_rn(v.z, v.w);
    *(uint2*)(out + i) = make_uint2(*(uint32_t*)&a, *(uint32_t*)&b);
}

// ---------------------------------------------------------------------------
// RoPE table + fused rope+fp16 split (q/k); V single fp16 convert
// ---------------------------------------------------------------------------
__global__ void rope_table_kernel(const int* __restrict__ pos,
                                  float* __restrict__ ct, float* __restrict__ st)
{
    int idx = blockIdx.x * blockDim.x + threadIdx.x;
    if (idx >= T_SEQ * (HD / 2)) return;
    int d = idx & 63;
    int t = idx >> 6;
    double inv = exp(-((double)(2 * d) / (double)HD) * 9.210340371976184);
    double ang = (double)pos[t] * inv;
    ct[idx] = (float)cos(ang);
    st[idx] = (float)sin(ang);
}

#define QSC (0.08838834764831845f * 1.4426950408889634f)  // 1/sqrt(HD) * log2(e)

__global__ void rope_split_kernel(const float* __restrict__ qkv,
                                  const float* __restrict__ ct,
                                  const float* __restrict__ st,
                                  __half* __restrict__ oh, __half* __restrict__ ol)
{
    int idx = blockIdx.x * blockDim.x + threadIdx.x;
    if (idx >= T_SEQ * (NH + NKV) * 16) return;
    int c16 = idx & 15;
    int h = (idx >> 4) % (NH + NKV);
    int t = idx / ((NH + NKV) * 16);
    int d = c16 * 4;
    const float* base = qkv + (size_t)t * QKV_N + h * HD;
    float4 x1 = *(const float4*)(base + d);
    float4 x2 = *(const float4*)(base + d + 64);
    float4 c = *(const float4*)(ct + t * 64 + d);
    float4 s = *(const float4*)(st + t * 64 + d);
    float4 y1, y2;
    y1.x = x1.x * c.x - x2.x * s.x;  y2.x = x2.x * c.x + x1.x * s.x;
    y1.y = x1.y * c.y - x2.y * s.y;  y2.y = x2.y * c.y + x1.y * s.y;
    y1.z = x1.z * c.z - x2.z * s.z;  y2.z = x2.z * c.z + x1.z * s.z;
    y1.w = x1.w * c.w - x2.w * s.w;  y2.w = x2.w * c.w + x1.w * s.w;
    if (h < NH) {
        y1.x *= QSC; y1.y *= QSC; y1.z *= QSC; y1.w *= QSC;
        y2.x *= QSC; y2.y *= QSC; y2.z *= QSC; y2.w *= QSC;
    }
    size_t o = (size_t)t * QKV_N + h * HD + d;
    split4h(y1, oh + o,      ol + o);
    split4h(y2, oh + o + 64, ol + o + 64);
}

__global__ void conv_v_kernel(const float* __restrict__ qkv,
                              __half* __restrict__ oh)
{
    int idx = blockIdx.x * blockDim.x + threadIdx.x;
    if (idx >= T_SEQ * 64) return;
    int t = idx >> 6;
    int c = (idx & 63) * 4 + (NH + NKV) * HD;
    size_t o = (size_t)t * QKV_N + c;
    float4 v = *(const float4*)(qkv + o);
    __half2 a = __floats2half2_rn(v.x, v.y);
    __half2 b = __floats2half2_rn(v.z, v.w);
    *(uint2*)(oh + o) = make_uint2(*(uint32_t*)&a, *(uint32_t*)&b);
}

// ===========================================================================
// 2-term fp16 GEMM (QKV): C = (Ah+Al) @ B^T + bias. 128x128, BK=32, 8 warps,
// 3-stage cp.async.
// ===========================================================================
#define GS 40
#define MATB (128 * GS * 2)
#define G2_STAGE (3 * 128 * GS)             // halves per stage
#define G2_SMEM  (3 * G2_STAGE * 2)         // 92160 bytes

__global__ void __launch_bounds__(256, 2)
gemm_2t(const __half* __restrict__ Ah_g, const __half* __restrict__ Al_g,
        const __half* __restrict__ B_g,
        const float* __restrict__ bias, float* __restrict__ C,
        int M, int N, int K)
{
    extern __shared__ __half smg[];
    const int tid = threadIdx.x, wid = tid >> 5, lane = tid & 31;
    const int bm = blockIdx.y * 128, bn = blockIdx.x * 128;
    const int wm = (wid & 3) * 32, wn = (wid >> 2) * 64;

    float acc[2][8][4];
#pragma unroll
    for (int i = 0; i < 2; i++)
#pragma unroll
        for (int n = 0; n < 8; n++)
#pragma unroll
            for (int e = 0; e < 4; e++) acc[i][n][e] = 0.f;

    const int S = K / 32;

    auto issue = [&](int s) {
        __half* base = smg + (s % 3) * G2_STAGE;
        const int k0 = s * 32;
#pragma unroll
        for (int i = 0; i < 12; i++) {
            int c = tid + i * 256;
            int mat = c >> 10;              // 0 Ah, 1 Al, 2 B
            int w = c & 1023;
            int row = w >> 3, cc = w & 7;
            const __half* src =
                (mat == 0) ? Ah_g + (size_t)(bm + row) * K + k0 + cc * 4 :
                (mat == 1) ? Al_g + (size_t)(bm + row) * K + k0 + cc * 4 :
                             B_g  + (size_t)(bn + row) * K + k0 + cc * 4;
            cp_async8(su32(base + mat * (128 * GS) + row * GS + cc * 4), src);
        }
    };

    issue(0); CP_COMMIT();
    if (S > 1) { issue(1); CP_COMMIT(); }

    const int a_r = lane & 15, a_k = (lane >> 4) * 8;
    const int b_n = ((lane >> 3) & 1) * 8 + (lane & 7), b_k = (lane >> 4) * 8;
    const uint32_t smb = su32(smg);
    const uint32_t a_base = 2 * ((wm + a_r) * GS + a_k);
    const uint32_t b_base = 2 * ((wn + b_n) * GS + b_k);

    for (int s = 0; s < S; s++) {
        if (s + 2 < S) { issue(s + 2); CP_COMMIT(); }
        STAGE_WAIT(s, S);
        __syncthreads();

        const uint32_t stb = smb + (s % 3) * (G2_STAGE * 2);
        const uint32_t pAh = stb + a_base;
        const uint32_t pAl = pAh + MATB;
        const uint32_t pB  = stb + 2 * MATB + b_base;

#pragma unroll
        for (int kk = 0; kk < 2; kk++) {
            const uint32_t ko = kk * 32;
            uint32_t ah[2][4], al[2][4];
            ldsm4(ah[0], pAh + ko);
            ldsm4(ah[1], pAh + ko + 16 * GS * 2);
            ldsm4(al[0], pAl + ko);
            ldsm4(al[1], pAl + ko + 16 * GS * 2);
#pragma unroll
            for (int np = 0; np < 4; np++) {
                uint32_t bh[4];
                ldsm4(bh, pB + ko + np * (16 * GS * 2));
                mma16816h(acc[0][np * 2],     ah[0], bh[0], bh[2]);
                mma16816h(acc[0][np * 2 + 1], ah[0], bh[1], bh[3]);
                mma16816h(acc[1][np * 2],     ah[1], bh[0], bh[2]);
                mma16816h(acc[1][np * 2 + 1], ah[1], bh[1], bh[3]);
                mma16816h(acc[0][np * 2],     al[0], bh[0], bh[2]);
                mma16816h(acc[0][np * 2 + 1], al[0], bh[1], bh[3]);
                mma16816h(acc[1][np * 2],     al[1], bh[0], bh[2]);
                mma16816h(acc[1][np * 2 + 1], al[1], bh[1], bh[3]);
            }
        }
        __syncthreads();
    }

    const int tr = lane >> 2;
    const int tc = (lane & 3) * 2;
#pragma unroll
    for (int i = 0; i < 2; i++) {
#pragma unroll
        for (int n = 0; n < 8; n++) {
            int col = bn + wn + n * 8 + tc;
            float bb0 = bias ? bias[col]     : 0.f;
            float bb1 = bias ? bias[col + 1] : 0.f;
            int row0 = bm + wm + i * 16 + tr;
            float2 v0 = make_float2(acc[i][n][0] + bb0, acc[i][n][1] + bb1);
            float2 v1 = make_float2(acc[i][n][2] + bb0, acc[i][n][3] + bb1);
            *(float2*)&C[(size_t)row0 * N + col]       = v0;
            *(float2*)&C[(size_t)(row0 + 8) * N + col] = v1;
        }
    }
}

// ===========================================================================
// 1-term fp16 GEMM (o-proj): C = A @ B^T. Same tiling, 3-stage.
// ===========================================================================
#define G1_STAGE (2 * 128 * GS)
#define G1_SMEM  (3 * G1_STAGE * 2)         // 61440 bytes

__global__ void __launch_bounds__(256, 2)
gemm_1t(const __half* __restrict__ A_g, const __half* __restrict__ B_g,
        float* __restrict__ C, int M, int N, int K)
{
    extern __shared__ __half smg[];
    const int tid = threadIdx.x, wid = tid >> 5, lane = tid & 31;
    const int bm = blockIdx.y * 128, bn = blockIdx.x * 128;
    const int wm = (wid & 3) * 32, wn = (wid >> 2) * 64;

    float acc[2][8][4];
#pragma unroll
    for (int i = 0; i < 2; i++)
#pragma unroll
        for (int n = 0; n < 8; n++)
#pragma unroll
            for (int e = 0; e < 4; e++) acc[i][n][e] = 0.f;

    const int S = K / 32;

    auto issue = [&](int s) {
        __half* base = smg + (s % 3) * G1_STAGE;
        const int k0 = s * 32;
#pragma unroll
        for (int i = 0; i < 8; i++) {
            int c = tid + i * 256;
            int mat = c >> 10;              // 0 A, 1 B
            int w = c & 1023;
            int row = w >> 3, cc = w & 7;
            const __half* src = (mat == 0)
                ? A_g + (size_t)(bm + row) * K + k0 + cc * 4
                : B_g + (size_t)(bn + row) * K + k0 + cc * 4;
            cp_async8(su32(base + mat * (128 * GS) + row * GS + cc * 4), src);
        }
    };

    issue(0); CP_COMMIT();
    if (S > 1) { issue(1); CP_COMMIT(); }

    const int a_r = lane & 15, a_k = (lane >> 4) * 8;
    const int b_n = ((lane >> 3) & 1) * 8 + (lane & 7), b_k = (lane >> 4) * 8;
    const uint32_t smb = su32(smg);
    const uint32_t a_base = 2 * ((wm + a_r) * GS + a_k);
    const uint32_t b_base = 2 * ((wn + b_n) * GS + b_k);

    for (int s = 0; s < S; s++) {
        if (s + 2 < S) { issue(s + 2); CP_COMMIT(); }
        STAGE_WAIT(s, S);
        __syncthreads();

        const uint32_t stb = smb + (s % 3) * (G1_STAGE * 2);
        const uint32_t pA = stb + a_base;
        const uint32_t pB = stb + MATB + b_base;

#pragma unroll
        for (int kk = 0; kk < 2; kk++) {
            const uint32_t ko = kk * 32;
            uint32_t ah[2][4];
            ldsm4(ah[0], pA + ko);
            ldsm4(ah[1], pA + ko + 16 * GS * 2);
#pragma unroll
            for (int np = 0; np < 4; np++) {
                uint32_t bh[4];
                ldsm4(bh, pB + ko + np * (16 * GS * 2));
                mma16816h(acc[0][np * 2],     ah[0], bh[0], bh[2]);
                mma16816h(acc[0][np * 2 + 1], ah[0], bh[1], bh[3]);
                mma16816h(acc[1][np * 2],     ah[1], bh[0], bh[2]);
                mma16816h(acc[1][np * 2 + 1], ah[1], bh[1], bh[3]);
            }
        }
        __syncthreads();
    }

    const int tr = lane >> 2;
    const int tc = (lane & 3) * 2;
#pragma unroll
    for (int i = 0; i < 2; i++) {
#pragma unroll
        for (int n = 0; n < 8; n++) {
            int col = bn + wn + n * 8 + tc;
            int row0 = bm + wm + i * 16 + tr;
            *(float2*)&C[(size_t)row0 * N + col] =
                make_float2(acc[i][n][0], acc[i][n][1]);
            *(float2*)&C[(size_t)(row0 + 8) * N + col] =
                make_float2(acc[i][n][2], acc[i][n][3]);
        }
    }
}

// ===========================================================================
// fp16 HMMA flash attention. Q single fp16 in registers; K hi/lo; V single.
// S = Qh(Kh+Kl), PV = P·Vh. 3-stage cp.async KV. Output single fp16.
// ===========================================================================
#define SKS 136
#define AT_QSZ (128 * SKS)                  // halves
#define AT_KSZ (64 * SKS)                   // halves per matrix
#define KMATB  (AT_KSZ * 2)                 // bytes per matrix
#define AT_STAGE (3 * AT_KSZ)               // halves per stage (Kh, Kl, Vh)
#define AT_STAGEB (AT_STAGE * 2)
#define AT_SMEM (AT_QSZ * 2 + 3 * AT_STAGEB)  // 34816 + 156672 = 191488 bytes

__global__ void __launch_bounds__(256, 1)
attn_mma(const __half* __restrict__ qkvh,
         const __half* __restrict__ qkvl,
         __half* __restrict__ out)
{
    extern __shared__ __half sma[];
    __half* Qs = sma;
    __half* KV = sma + AT_QSZ;

    const int tid = threadIdx.x, wid = tid >> 5, lane = tid & 31;
    const int h = blockIdx.y;
    const int qt = (int)gridDim.x - 1 - (int)blockIdx.x;   // heavy tiles first
    const int qbase = qt * 128;
    const int g = h >> 3;
    const int qoff = h * HD;
    const int koff = NH * HD + g * HD;
    const int voff = (NH + NKV) * HD + g * HD;

    // ---- load Q tile to smem ----
#pragma unroll
    for (int i = 0; i < 8; i++) {
        int c = tid + i * 256;
        int row = c >> 4, cc = c & 15;
        const __half* src = qkvh + (size_t)(qbase + row) * QKV_N + qoff + cc * 8;
        *(uint4*)(Qs + row * SKS + cc * 8) = *(const uint4*)src;
    }

    auto load_kv = [&](int kt) {
        const int kbase = kt * 64;
        __half* base = KV + (kt % 3) * AT_STAGE;
#pragma unroll
        for (int i = 0; i < 12; i++) {
            int c = tid + i * 256;        // 3072 chunks of 16B
            int mat = c >> 10;            // 0 Kh, 1 Kl, 2 Vh
            int w = c & 1023;
            int row = w >> 4, cc = w & 15;
            const __half* src =
                (mat == 0) ? qkvh + (size_t)(kbase + row) * QKV_N + koff + cc * 8 :
                (mat == 1) ? qkvl + (size_t)(kbase + row) * QKV_N + koff + cc * 8 :
                             qkvh + (size_t)(kbase + row) * QKV_N + voff + cc * 8;
            cp_async16(su32(base + mat * AT_KSZ + row * SKS + cc * 8), src);
        }
    };

    const int nkt = 2 * qt + 2;
    load_kv(0); CP_COMMIT();
    load_kv(1); CP_COMMIT();     // nkt >= 2 always

    const int wq = wid * 16;
    const int a_r = lane & 15, a_k = (lane >> 4) * 8;
    const int b_n = ((lane >> 3) & 1) * 8 + (lane & 7), b_k = (lane >> 4) * 8;

    const uint32_t smb = su32(sma);
    const uint32_t pQ = smb + 2 * ((wq + a_r) * SKS + a_k);
    const uint32_t bk_base = 2 * (b_n * SKS + b_k);

    __syncthreads();   // Q stores visible
    uint32_t qf[8][4];
#pragma unroll
    for (int kk = 0; kk < 8; kk++) ldsm4(qf[kk], pQ + kk * 32);

    float o[16][4];
#pragma unroll
    for (int d = 0; d < 16; d++)
#pragma unroll
        for (int e = 0; e < 4; e++) o[d][e] = 0.f;
    float m0 = -1e30f, m1 = -1e30f, l0 = 0.f, l1 = 0.f;

    for (int kt = 0; kt < nkt; kt++) {
        if (kt + 2 < nkt) { load_kv(kt + 2); CP_COMMIT(); }
        STAGE_WAIT(kt, nkt);
        __syncthreads();

        const uint32_t kvb = smb + AT_QSZ * 2 + (kt % 3) * AT_STAGEB;
        const uint32_t pK = kvb + bk_base;
        const uint32_t pV = kvb + 2 * KMATB + bk_base;

        // ---- S = Qh @ (Kh + Kl)^T ----
        float s[8][4];
#pragma unroll
        for (int n = 0; n < 8; n++)
#pragma unroll
            for (int e = 0; e < 4; e++) s[n][e] = 0.f;

#pragma unroll
        for (int kk = 0; kk < 8; kk++) {
            const uint32_t ko = kk * 32;
            uint32_t kh[4][4], kl[4][4];
#pragma unroll
            for (int g4 = 0; g4 < 4; g4++) {
                ldsm4(kh[g4], pK + ko + g4 * (16 * SKS * 2));
                ldsm4(kl[g4], pK + KMATB + ko + g4 * (16 * SKS * 2));
            }
#pragma unroll
            for (int g4 = 0; g4 < 4; g4++) {
                mma16816h(s[g4 * 2],     qf[kk], kh[g4][0], kh[g4][2]);
                mma16816h(s[g4 * 2 + 1], qf[kk], kh[g4][1], kh[g4][3]);
            }
#pragma unroll
            for (int g4 = 0; g4 < 4; g4++) {
                mma16816h(s[g4 * 2],     qf[kk], kl[g4][0], kl[g4][2]);
                mma16816h(s[g4 * 2 + 1], qf[kk], kl[g4][1], kl[g4][3]);
            }
        }

        // ---- causal mask ----
        const int kbase = kt * 64;
        if (kt >= 2 * qt) {
            int rg0 = qbase + wq + (lane >> 2);
#pragma unroll
            for (int n = 0; n < 8; n++) {
                int cg = kbase + n * 8 + (lane & 3) * 2;
                if (cg > rg0)         s[n][0] = -1e30f;
                if (cg + 1 > rg0)     s[n][1] = -1e30f;
                if (cg > rg0 + 8)     s[n][2] = -1e30f;
                if (cg + 1 > rg0 + 8) s[n][3] = -1e30f;
            }
        }

        // ---- online softmax (exp2 domain) ----
        float mx0 = -1e30f, mx1 = -1e30f;
#pragma unroll
        for (int n = 0; n < 8; n++) {
            mx0 = fmaxf(mx0, fmaxf(s[n][0], s[n][1]));
            mx1 = fmaxf(mx1, fmaxf(s[n][2], s[n][3]));
        }
        mx0 = fmaxf(mx0, __shfl_xor_sync(0xffffffffu, mx0, 1));
        mx0 = fmaxf(mx0, __shfl_xor_sync(0xffffffffu, mx0, 2));
        mx1 = fmaxf(mx1, __shfl_xor_sync(0xffffffffu, mx1, 1));
        mx1 = fmaxf(mx1, __shfl_xor_sync(0xffffffffu, mx1, 2));
        float mn0 = fmaxf(m0, mx0), mn1 = fmaxf(m1, mx1);
        float c0 = ex2f(m0 - mn0), c1 = ex2f(m1 - mn1);
        float rs0 = 0.f, rs1 = 0.f;
#pragma unroll
        for (int n = 0; n < 8; n++) {
            s[n][0] = ex2f(s[n][0] - mn0); rs0 += s[n][0];
            s[n][1] = ex2f(s[n][1] - mn0); rs0 += s[n][1];
            s[n][2] = ex2f(s[n][2] - mn1); rs1 += s[n][2];
            s[n][3] = ex2f(s[n][3] - mn1); rs1 += s[n][3];
        }
        rs0 += __shfl_xor_sync(0xffffffffu, rs0, 1);
        rs0 += __shfl_xor_sync(0xffffffffu, rs0, 2);
        rs1 += __shfl_xor_sync(0xffffffffu, rs1, 1);
        rs1 += __shfl_xor_sync(0xffffffffu, rs1, 2);
        l0 = l0 * c0 + rs0; l1 = l1 * c1 + rs1;
        m0 = mn0; m1 = mn1;
#pragma unroll
        for (int d = 0; d < 16; d++) {
            o[d][0] *= c0; o[d][1] *= c0;
            o[d][2] *= c1; o[d][3] *= c1;
        }

        // ---- P (single fp16, A-layout) ----
        uint32_t aP[4][4];
#pragma unroll
        for (int kb = 0; kb < 4; kb++) {
            float* f0 = s[2 * kb];
            float* f1 = s[2 * kb + 1];
            aP[kb][0] = packh(f0[0], f0[1]);
            aP[kb][1] = packh(f0[2], f0[3]);
            aP[kb][2] = packh(f1[0], f1[1]);
            aP[kb][3] = packh(f1[2], f1[3]);
        }

        // ---- O += P @ Vh ----
#pragma unroll
        for (int kb = 0; kb < 4; kb++) {
            const uint32_t pvb = pV + kb * (16 * SKS * 2);
#pragma unroll
            for (int dp = 0; dp < 4; dp++) {
                uint32_t vh0[4], vh1[4];
                ldsm4t(vh0, pvb + (2 * dp) * 32);
                ldsm4t(vh1, pvb + (2 * dp + 1) * 32);
                mma16816h(o[4 * dp],     aP[kb], vh0[0], vh0[1]);
                mma16816h(o[4 * dp + 1], aP[kb], vh0[2], vh0[3]);
                mma16816h(o[4 * dp + 2], aP[kb], vh1[0], vh1[1]);
                mma16816h(o[4 * dp + 3], aP[kb], vh1[2], vh1[3]);
            }
        }
        __syncthreads();
    }

    // ---- epilogue: O/l -> single fp16 ----
    float inv0 = 1.f / l0, inv1 = 1.f / l1;
    int row0 = qbase + wq + (lane >> 2);
    int colb = h * HD + (lane & 3) * 2;
#pragma unroll
    for (int dg = 0; dg < 16; dg++) {
        int col = colb + dg * 8;
        __half2 hA = __floats2half2_rn(o[dg][0] * inv0, o[dg][1] * inv0);
        __half2 hB = __floats2half2_rn(o[dg][2] * inv1, o[dg][3] * inv1);
        *(__half2*)(out + (size_t)row0 * HID + col)       = hA;
        *(__half2*)(out + (size_t)(row0 + 8) * HID + col) = hB;
    }
}

// ---------------------------------------------------------------------------
extern "C" void kernel_launch(void* const* d_in, const int* in_sizes, int n_in,
                              void* d_out, int out_size)
{
    const int*   positions = (const int*)d_in[0];
    const float* hidden    = (const float*)d_in[1];
    const float* w_qkv     = (const float*)d_in[2];
    const float* b_qkv     = (const float*)d_in[3];
    const float* w_o       = (const float*)d_in[4];
    float* out = (float*)d_out;

    float *qkv, *ct, *st;
    __half *hidh, *hidl, *wq, *wo, *qkvh, *qkvl, *attn;
    cudaGetSymbolAddress((void**)&qkv,  g_qkv);
    cudaGetSymbolAddress((void**)&ct,   g_cos);
    cudaGetSymbolAddress((void**)&st,   g_sin);
    cudaGetSymbolAddress((void**)&hidh, g_hidh);
    cudaGetSymbolAddress((void**)&hidl, g_hidl);
    cudaGetSymbolAddress((void**)&wq,   g_wq);
    cudaGetSymbolAddress((void**)&wo,   g_wo);
    cudaGetSymbolAddress((void**)&qkvh, g_qkvh);
    cudaGetSymbolAddress((void**)&qkvl, g_qkvl);
    cudaGetSymbolAddress((void**)&attn, g_attn);

    cudaFuncSetAttribute(gemm_2t,
                         cudaFuncAttributeMaxDynamicSharedMemorySize, G2_SMEM);
    cudaFuncSetAttribute(gemm_1t,
                         cudaFuncAttributeMaxDynamicSharedMemorySize, G1_SMEM);
    cudaFuncSetAttribute(attn_mma,
                         cudaFuncAttributeMaxDynamicSharedMemorySize, AT_SMEM);

    // 0) prep inputs
    {
        int n1 = T_SEQ * HID;
        split_h<<<n1 / 1024, 256>>>(hidden, hidh, hidl, n1);
        int n2 = QKV_N * HID;
        conv_h<<<n2 / 1024, 256>>>(w_qkv, wq, n2);
        int n3 = HID * HID;
        conv_h<<<n3 / 1024, 256>>>(w_o, wo, n3);
    }

    // 1) qkv = hidden @ w_qkv^T + b_qkv (fp32 out)
    dim3 g1(QKV_N / 128, T_SEQ / 128);
    gemm_2t<<<g1, 256, G2_SMEM>>>(hidh, hidl, wq, b_qkv, qkv,
                                  T_SEQ, QKV_N, HID);

    // 2) RoPE + fp16 splits
    int nt = T_SEQ * (HD / 2);
    rope_table_kernel<<<(nt + 255) / 256, 256>>>(positions, ct, st);
    int nr = T_SEQ * (NH + NKV) * 16;
    rope_split_kernel<<<nr / 256, 256>>>(qkv, ct, st, qkvh, qkvl);
    int nv = T_SEQ * 64;
    conv_v_kernel<<<nv / 256, 256>>>(qkv, qkvh);

    // 3) flash attention (fp16 HMMA), single-fp16 output
    attn_mma<<<dim3(T_SEQ / 128, NH), 256, AT_SMEM>>>(qkvh, qkvl, attn);

    // 4) out = attn @ w_o^T (1-term)
    dim3 g2(HID / 128, T_SEQ / 128);
    gemm_1t<<<g2, 256, G1_SMEM>>>(attn, wo, out, T_SEQ, HID, HID);
}